// round 1
// baseline (speedup 1.0000x reference)
#include <cuda_runtime.h>
#include <cstdint>

// Problem constants (fixed shapes from setup_inputs)
#define NBATCH 4
#define LSEQ   8192
#define HEADS  16
#define EDIM   64
#define DDIM   64
#define CHK    128
#define NCH    64                      // LSEQ / CHK
#define NTILE  (NBATCH*HEADS*NCH)      // 4096
#define NPAIR  (NBATCH*HEADS)          // 64
#define ROWSTR (HEADS*EDIM)            // 1024 floats between consecutive l

// Scratch: per-(n,h,chunk) K^T V partial state (later exclusive prefix) + K colsums
__device__ float g_S [NTILE][EDIM*DDIM];   // 64 MB
__device__ float g_ks[NTILE][EDIM];        // 1 MB

__device__ __forceinline__ float featmap(float x) {
    // elu(x)+1 : x>0 -> x+1 ; else exp(x)
    return x > 0.f ? x + 1.f : __expf(x);
}

// ---------------------------------------------------------------------------
// Pass 1: per-chunk S_c[e][d] = sum_l phi(k[l])[e] * v[l][d]; ksum_c[e]
// grid = 4096, block = 256
// ---------------------------------------------------------------------------
__global__ void __launch_bounds__(256) k_pass1(const float* __restrict__ keys,
                                               const float* __restrict__ values) {
    extern __shared__ float sm[];
    float* ks = sm;              // [128][65]
    float* vs = sm + 128*65;     // [128][65]

    const int tile = blockIdx.x;
    const int c  = tile & (NCH - 1);
    const int nh = tile >> 6;
    const int h  = nh & (HEADS - 1);
    const int n  = nh >> 4;
    const int tid = threadIdx.x;

    const size_t base = (((size_t)n * LSEQ + (size_t)c * CHK) * HEADS + h) * EDIM;

    // load chunk: 128 rows x 64 floats, float4 per thread
    for (int p = tid; p < CHK * 16; p += 256) {
        const int row = p >> 4;
        const int c4  = (p & 15) << 2;
        const float4 kv = *(const float4*)(keys   + base + (size_t)row * ROWSTR + c4);
        const float4 vv = *(const float4*)(values + base + (size_t)row * ROWSTR + c4);
        float* kr = ks + row * 65 + c4;
        kr[0] = featmap(kv.x); kr[1] = featmap(kv.y);
        kr[2] = featmap(kv.z); kr[3] = featmap(kv.w);
        float* vr = vs + row * 65 + c4;
        vr[0] = vv.x; vr[1] = vv.y; vr[2] = vv.z; vr[3] = vv.w;
    }
    __syncthreads();

    // S tile: thread (et,dt) owns e rows et*4..+3, d cols dt+16m (m<4)
    const int et = tid >> 4;
    const int dt = tid & 15;
    float acc[4][4] = {};
    for (int l = 0; l < CHK; l++) {
        float kk[4], vv[4];
        #pragma unroll
        for (int i = 0; i < 4; i++) kk[i] = ks[l * 65 + et * 4 + i];
        #pragma unroll
        for (int m = 0; m < 4; m++) vv[m] = vs[l * 65 + dt + 16 * m];
        #pragma unroll
        for (int i = 0; i < 4; i++)
            #pragma unroll
            for (int m = 0; m < 4; m++)
                acc[i][m] = fmaf(kk[i], vv[m], acc[i][m]);
    }
    float* So = g_S[tile];
    #pragma unroll
    for (int i = 0; i < 4; i++)
        #pragma unroll
        for (int m = 0; m < 4; m++)
            So[(et * 4 + i) * DDIM + dt + 16 * m] = acc[i][m];

    if (tid < EDIM) {
        float s = 0.f;
        for (int l = 0; l < CHK; l++) s += ks[l * 65 + tid];
        g_ks[tile][tid] = s;
    }
}

// ---------------------------------------------------------------------------
// Pass 2: in-place exclusive prefix over chunks, per (n,h). grid = 64
// ---------------------------------------------------------------------------
__global__ void __launch_bounds__(256) k_pass2() {
    const int nh  = blockIdx.x;
    const int tid = threadIdx.x;
    const int base = nh * NCH;

    float run[16];
    #pragma unroll
    for (int i = 0; i < 16; i++) run[i] = 0.f;
    float krun = 0.f;

    for (int c = 0; c < NCH; c++) {
        float* Sp = g_S[base + c];
        #pragma unroll
        for (int i = 0; i < 16; i++) {
            const int idx = tid + 256 * i;
            const float t = Sp[idx];
            Sp[idx] = run[i];
            run[i] += t;
        }
        if (tid < EDIM) {
            const float t = g_ks[base + c][tid];
            g_ks[base + c][tid] = krun;
            krun += t;
        }
    }
}

// ---------------------------------------------------------------------------
// Pass 3: out = (q @ S_prefix + tril(q k^T) @ v) / (q . ksum_prefix + rowsum)
// grid = 4096, block = 256
// ---------------------------------------------------------------------------
__global__ void __launch_bounds__(256) k_pass3(const float* __restrict__ Qg,
                                               const float* __restrict__ Kg,
                                               const float* __restrict__ Vg,
                                               float* __restrict__ out) {
    extern __shared__ float sm[];
    float* q    = sm;                    // [128][65]
    float* k    = q  + 128*65;           // [128][65]
    float* v    = k  + 128*65;           // [128][65]
    float* S    = v  + 128*65;           // [64][65]
    float* sc   = S  + 64*65;            // [128][129]
    float* ksum = sc + 128*129;          // [64]
    float* dnm  = ksum + 64;             // [128]

    const int tile = blockIdx.x;
    const int c  = tile & (NCH - 1);
    const int nh = tile >> 6;
    const int h  = nh & (HEADS - 1);
    const int n  = nh >> 4;
    const int tid = threadIdx.x;

    const size_t base = (((size_t)n * LSEQ + (size_t)c * CHK) * HEADS + h) * EDIM;

    for (int p = tid; p < CHK * 16; p += 256) {
        const int row = p >> 4;
        const int c4  = (p & 15) << 2;
        const float4 qv = *(const float4*)(Qg + base + (size_t)row * ROWSTR + c4);
        const float4 kv = *(const float4*)(Kg + base + (size_t)row * ROWSTR + c4);
        const float4 vv = *(const float4*)(Vg + base + (size_t)row * ROWSTR + c4);
        float* qr = q + row * 65 + c4;
        qr[0] = featmap(qv.x); qr[1] = featmap(qv.y);
        qr[2] = featmap(qv.z); qr[3] = featmap(qv.w);
        float* kr = k + row * 65 + c4;
        kr[0] = featmap(kv.x); kr[1] = featmap(kv.y);
        kr[2] = featmap(kv.z); kr[3] = featmap(kv.w);
        float* vr = v + row * 65 + c4;
        vr[0] = vv.x; vr[1] = vv.y; vr[2] = vv.z; vr[3] = vv.w;
    }
    {
        const float* Sg = g_S[tile];
        for (int p = tid; p < EDIM * DDIM; p += 256)
            S[(p >> 6) * 65 + (p & 63)] = Sg[p];
        if (tid < EDIM) ksum[tid] = g_ks[tile][tid];
    }
    __syncthreads();

    // --- Stage A: scores = tril(q @ k^T), 8x8 tile per thread --------------
    {
        const int it = tid >> 4;          // rows it*8..+7
        const int jt = tid & 15;          // cols jt + 16m, m<8
        float acc[8][8] = {};
        for (int e = 0; e < EDIM; e++) {
            float qr[8], kr[8];
            #pragma unroll
            for (int i = 0; i < 8; i++) qr[i] = q[(it * 8 + i) * 65 + e];
            #pragma unroll
            for (int m = 0; m < 8; m++) kr[m] = k[(jt + 16 * m) * 65 + e];
            #pragma unroll
            for (int i = 0; i < 8; i++)
                #pragma unroll
                for (int m = 0; m < 8; m++)
                    acc[i][m] = fmaf(qr[i], kr[m], acc[i][m]);
        }
        #pragma unroll
        for (int i = 0; i < 8; i++)
            #pragma unroll
            for (int m = 0; m < 8; m++) {
                const int row = it * 8 + i;
                const int col = jt + 16 * m;
                sc[row * 129 + col] = (col <= row) ? acc[i][m] : 0.f;
            }
    }
    __syncthreads();

    // --- Stage B: out = scores @ v + q @ S,  8x4 tile per thread -----------
    const int rt = tid >> 4;              // rows rt*8..+7
    const int dt = tid & 15;              // cols dt + 16m, m<4
    float acc[8][4] = {};
    for (int j = 0; j < CHK; j++) {
        float sr[8], vr[4];
        #pragma unroll
        for (int i = 0; i < 8; i++) sr[i] = sc[(rt * 8 + i) * 129 + j];
        #pragma unroll
        for (int m = 0; m < 4; m++) vr[m] = v[j * 65 + dt + 16 * m];
        #pragma unroll
        for (int i = 0; i < 8; i++)
            #pragma unroll
            for (int m = 0; m < 4; m++)
                acc[i][m] = fmaf(sr[i], vr[m], acc[i][m]);
    }
    for (int e = 0; e < EDIM; e++) {
        float qr[8], Sr[4];
        #pragma unroll
        for (int i = 0; i < 8; i++) qr[i] = q[(rt * 8 + i) * 65 + e];
        #pragma unroll
        for (int m = 0; m < 4; m++) Sr[m] = S[e * 65 + dt + 16 * m];
        #pragma unroll
        for (int i = 0; i < 8; i++)
            #pragma unroll
            for (int m = 0; m < 4; m++)
                acc[i][m] = fmaf(qr[i], Sr[m], acc[i][m]);
    }

    // --- denominator: rowsum(scores) + q . ksum ----------------------------
    if (tid < CHK) {
        float s = 0.f;
        for (int j = 0; j < CHK; j++) s += sc[tid * 129 + j];
        for (int e = 0; e < EDIM; e++) s = fmaf(q[tid * 65 + e], ksum[e], s);
        dnm[tid] = 1.f / (s + 1e-6f);
    }
    __syncthreads();

    const size_t obase = (((size_t)n * LSEQ + (size_t)c * CHK) * HEADS + h) * DDIM;
    #pragma unroll
    for (int i = 0; i < 8; i++) {
        const int row = rt * 8 + i;
        const float z = dnm[row];
        #pragma unroll
        for (int m = 0; m < 4; m++)
            out[obase + (size_t)row * ROWSTR + dt + 16 * m] = acc[i][m] * z;
    }
}

// ---------------------------------------------------------------------------
extern "C" void kernel_launch(void* const* d_in, const int* in_sizes, int n_in,
                              void* d_out, int out_size) {
    const float* Q = (const float*)d_in[0];
    const float* K = (const float*)d_in[1];
    const float* V = (const float*)d_in[2];
    float* out = (float*)d_out;

    const int smem1 = 2 * 128 * 65 * (int)sizeof(float);                       // 66560
    const int smem3 = (3 * 128 * 65 + 64 * 65 + 128 * 129 + 64 + 128)
                      * (int)sizeof(float);                                    // 183296

    cudaFuncSetAttribute(k_pass1, cudaFuncAttributeMaxDynamicSharedMemorySize, smem1);
    cudaFuncSetAttribute(k_pass3, cudaFuncAttributeMaxDynamicSharedMemorySize, smem3);

    k_pass1<<<NTILE, 256, smem1>>>(K, V);
    k_pass2<<<NPAIR, 256>>>();
    k_pass3<<<NTILE, 256, smem3>>>(Q, K, V, out);
}

// round 3
// speedup vs baseline: 1.6776x; 1.6776x over previous
#include <cuda_runtime.h>
#include <cuda_bf16.h>
#include <cstdint>

// Problem constants (fixed shapes)
#define NBATCH 4
#define LSEQ   8192
#define HEADS  16
#define EDIM   64
#define DDIM   64
#define CHK    128
#define NCH    64
#define NTILE  (NBATCH*HEADS*NCH)      // 4096
#define ROWSTR (HEADS*EDIM)            // 1024

__device__ float g_S [NTILE][EDIM*DDIM];   // 64 MB
__device__ float g_ks[NTILE][EDIM];        // 1 MB

__device__ __forceinline__ float featmap(float x) {
    return x > 0.f ? x + 1.f : __expf(x);
}

__device__ __forceinline__ uint32_t smem_u32(const void* p) {
    return (uint32_t)__cvta_generic_to_shared(p);
}

// ---- warp-level tensor core primitives (base ISA, sm_80+) -----------------
__device__ __forceinline__ void mma16816(float* c, const uint32_t* a, const uint32_t* b) {
    asm volatile(
        "mma.sync.aligned.m16n8k16.row.col.f32.bf16.bf16.f32 "
        "{%0,%1,%2,%3}, {%4,%5,%6,%7}, {%8,%9}, {%0,%1,%2,%3};"
        : "+f"(c[0]), "+f"(c[1]), "+f"(c[2]), "+f"(c[3])
        : "r"(a[0]), "r"(a[1]), "r"(a[2]), "r"(a[3]), "r"(b[0]), "r"(b[1]));
}
__device__ __forceinline__ void ldsm_x4(uint32_t* r, uint32_t addr) {
    asm volatile("ldmatrix.sync.aligned.m8n8.x4.shared.b16 {%0,%1,%2,%3}, [%4];"
                 : "=r"(r[0]), "=r"(r[1]), "=r"(r[2]), "=r"(r[3]) : "r"(addr));
}
__device__ __forceinline__ void ldsm_x4t(uint32_t* r, uint32_t addr) {
    asm volatile("ldmatrix.sync.aligned.m8n8.x4.trans.shared.b16 {%0,%1,%2,%3}, [%4];"
                 : "=r"(r[0]), "=r"(r[1]), "=r"(r[2]), "=r"(r[3]) : "r"(addr));
}
__device__ __forceinline__ void ldsm_x2(uint32_t* r, uint32_t addr) {
    asm volatile("ldmatrix.sync.aligned.m8n8.x2.shared.b16 {%0,%1}, [%2];"
                 : "=r"(r[0]), "=r"(r[1]) : "r"(addr));
}
__device__ __forceinline__ void ldsm_x2t(uint32_t* r, uint32_t addr) {
    asm volatile("ldmatrix.sync.aligned.m8n8.x2.trans.shared.b16 {%0,%1}, [%2];"
                 : "=r"(r[0]), "=r"(r[1]) : "r"(addr));
}

__device__ __forceinline__ void split_pack(float a, float b, uint32_t& hi, uint32_t& lo) {
    __nv_bfloat16 ah = __float2bfloat16(a), bh = __float2bfloat16(b);
    __nv_bfloat16 al = __float2bfloat16(a - __bfloat162float(ah));
    __nv_bfloat16 bl = __float2bfloat16(b - __bfloat162float(bh));
    hi = ((uint32_t)__bfloat16_as_ushort(bh) << 16) | (uint32_t)__bfloat16_as_ushort(ah);
    lo = ((uint32_t)__bfloat16_as_ushort(bl) << 16) | (uint32_t)__bfloat16_as_ushort(al);
}
__device__ __forceinline__ void split1(float a, __nv_bfloat16& hi, __nv_bfloat16& lo) {
    hi = __float2bfloat16(a);
    lo = __float2bfloat16(a - __bfloat162float(hi));
}

// row strides (bf16 elements)
#define QS  72     // Q/K/V/S row stride
#define SCS 136    // scores row stride

// ---------------------------------------------------------------------------
// Pass 1 (tensor): S_c[e][d] = sum_l phi(k)[e] v[d]; ksum_c[e]
// block = 128 (4 warps), grid = 4096. smem: K,V hi/lo planes.
// ---------------------------------------------------------------------------
#define P1_KH 0
#define P1_KL 18432
#define P1_VH 36864
#define P1_VL 55296
#define P1_SMEM 73728

__global__ void __launch_bounds__(128) k_pass1(const float* __restrict__ keys,
                                               const float* __restrict__ values) {
    extern __shared__ char smc[];
    const uint32_t smb = smem_u32(smc);

    const int tile = blockIdx.x;
    const int c  = tile & (NCH - 1);
    const int nh = tile >> 6;
    const int h  = nh & (HEADS - 1);
    const int n  = nh >> 4;
    const int tid = threadIdx.x;
    const int wid = tid >> 5;
    const int lid = tid & 31;

    const size_t base = (((size_t)n * LSEQ + (size_t)c * CHK) * HEADS + h) * EDIM;

    for (int p = tid; p < CHK * 16; p += 128) {
        const int row = p >> 4;
        const int c4  = (p & 15) << 2;
        const float4 kv = *(const float4*)(keys   + base + (size_t)row * ROWSTR + c4);
        const float4 vv = *(const float4*)(values + base + (size_t)row * ROWSTR + c4);
        const uint32_t off = (uint32_t)(row * QS + c4) * 2;
        uint32_t h01, l01, h23, l23;
        split_pack(featmap(kv.x), featmap(kv.y), h01, l01);
        split_pack(featmap(kv.z), featmap(kv.w), h23, l23);
        *(uint32_t*)(smc + P1_KH + off)     = h01;
        *(uint32_t*)(smc + P1_KH + off + 4) = h23;
        *(uint32_t*)(smc + P1_KL + off)     = l01;
        *(uint32_t*)(smc + P1_KL + off + 4) = l23;
        split_pack(vv.x, vv.y, h01, l01);
        split_pack(vv.z, vv.w, h23, l23);
        *(uint32_t*)(smc + P1_VH + off)     = h01;
        *(uint32_t*)(smc + P1_VH + off + 4) = h23;
        *(uint32_t*)(smc + P1_VL + off)     = l01;
        *(uint32_t*)(smc + P1_VL + off + 4) = l23;
    }
    __syncthreads();

    // ksum: threads 0..63 sum column e of featmap(K)
    if (tid < EDIM) {
        float s = 0.f;
        for (int l = 0; l < CHK; l++) {
            s += __bfloat162float(*(const __nv_bfloat16*)(smc + P1_KH + (l * QS + tid) * 2))
               + __bfloat162float(*(const __nv_bfloat16*)(smc + P1_KL + (l * QS + tid) * 2));
        }
        g_ks[tile][tid] = s;
    }

    // MMA: S[64,64] = K^T @ V (k = 128), warp tile 16 x 64
    const int m0 = wid * 16;
    float C[8][4] = {};
    const int gi  = lid & 7;
    const int grp = lid >> 3;
    for (int kk = 0; kk < CHK; kk += 16) {
        uint32_t ah[4], al[4];
        {   // A = K^T via trans ldmatrix on K rows
            const int row  = kk + ((grp & 2) ? 8 : 0) + gi;
            const int colm = m0 + ((grp & 1) ? 8 : 0);
            const uint32_t off = (uint32_t)(row * QS + colm) * 2;
            ldsm_x4t(ah, smb + P1_KH + off);
            ldsm_x4t(al, smb + P1_KL + off);
        }
        const int brow = kk + ((grp & 1) ? 8 : 0) + gi;
        #pragma unroll
        for (int nt = 0; nt < 8; nt++) {
            const uint32_t boff = (uint32_t)(brow * QS + nt * 8) * 2;
            uint32_t bh[2], bl[2];
            ldsm_x2t(bh, smb + P1_VH + boff);
            ldsm_x2t(bl, smb + P1_VL + boff);
            mma16816(C[nt], ah, bh);
            mma16816(C[nt], ah, bl);
            mma16816(C[nt], al, bh);
        }
    }

    // store C -> g_S
    float* So = g_S[tile];
    const int e0 = m0 + (lid >> 2);
    const int e1 = e0 + 8;
    #pragma unroll
    for (int nt = 0; nt < 8; nt++) {
        const int d = nt * 8 + (lid & 3) * 2;
        *(float2*)(So + e0 * 64 + d) = make_float2(C[nt][0], C[nt][1]);
        *(float2*)(So + e1 * 64 + d) = make_float2(C[nt][2], C[nt][3]);
    }
}

// ---------------------------------------------------------------------------
// Pass 2: exclusive prefix over chunks. grid = (16,64), block = 256.
// ---------------------------------------------------------------------------
__global__ void __launch_bounds__(256) k_pass2() {
    const int nh  = blockIdx.y;
    const int idx = blockIdx.x * 256 + threadIdx.x;
    const int base = nh * NCH;

    float run = 0.f;
    #pragma unroll 4
    for (int c = 0; c < NCH; c++) {
        const float t = g_S[base + c][idx];
        g_S[base + c][idx] = run;
        run += t;
    }
    if (blockIdx.x == 0 && threadIdx.x < EDIM) {
        const int e = threadIdx.x;
        float kr = 0.f;
        #pragma unroll 4
        for (int c = 0; c < NCH; c++) {
            const float t = g_ks[base + c][e];
            g_ks[base + c][e] = kr;
            kr += t;
        }
    }
}

// ---------------------------------------------------------------------------
// Pass 3 (tensor): out = (Qf@S + tril(Qf Kf^T)@V) / (Qf.ksum + rowsum)
// block = 256 (8 warps), grid = 4096.
// ---------------------------------------------------------------------------
#define QH_OFF   0
#define QL_OFF   18432
#define KH_OFF   36864
#define KL_OFF   55296
#define VH_OFF   73728
#define VL_OFF   92160
#define SH_OFF   110592
#define SL_OFF   119808
#define SCH_OFF  129024
#define SCL_OFF  163840
#define KSUM_OFF 198656
#define DNM_OFF  198912
#define P3_SMEM  199424
#define OUTB_OFF SCH_OFF   // reuse scores-hi plane for f32 [128][68] out staging

__global__ void __launch_bounds__(256) k_pass3(const float* __restrict__ Qg,
                                               const float* __restrict__ Kg,
                                               const float* __restrict__ Vg,
                                               float* __restrict__ out) {
    extern __shared__ char smc[];
    const uint32_t smb = smem_u32(smc);
    float* ksum = (float*)(smc + KSUM_OFF);
    float* dnm  = (float*)(smc + DNM_OFF);
    float* outb = (float*)(smc + OUTB_OFF);

    const int tile = blockIdx.x;
    const int c  = tile & (NCH - 1);
    const int nh = tile >> 6;
    const int h  = nh & (HEADS - 1);
    const int n  = nh >> 4;
    const int tid = threadIdx.x;
    const int wid = tid >> 5;
    const int lid = tid & 31;

    const size_t base = (((size_t)n * LSEQ + (size_t)c * CHK) * HEADS + h) * EDIM;

    if (tid < EDIM) ksum[tid] = g_ks[tile][tid];

    // ---- stage Q,K (featmap, hi/lo), V (hi/lo) ----
    for (int p = tid; p < CHK * 16; p += 256) {
        const int row = p >> 4;
        const int c4  = (p & 15) << 2;
        const size_t g = base + (size_t)row * ROWSTR + c4;
        const float4 qv = *(const float4*)(Qg + g);
        const float4 kv = *(const float4*)(Kg + g);
        const float4 vv = *(const float4*)(Vg + g);
        const uint32_t off = (uint32_t)(row * QS + c4) * 2;
        uint32_t h01, l01, h23, l23;
        split_pack(featmap(qv.x), featmap(qv.y), h01, l01);
        split_pack(featmap(qv.z), featmap(qv.w), h23, l23);
        *(uint32_t*)(smc + QH_OFF + off)     = h01;
        *(uint32_t*)(smc + QH_OFF + off + 4) = h23;
        *(uint32_t*)(smc + QL_OFF + off)     = l01;
        *(uint32_t*)(smc + QL_OFF + off + 4) = l23;
        split_pack(featmap(kv.x), featmap(kv.y), h01, l01);
        split_pack(featmap(kv.z), featmap(kv.w), h23, l23);
        *(uint32_t*)(smc + KH_OFF + off)     = h01;
        *(uint32_t*)(smc + KH_OFF + off + 4) = h23;
        *(uint32_t*)(smc + KL_OFF + off)     = l01;
        *(uint32_t*)(smc + KL_OFF + off + 4) = l23;
        split_pack(vv.x, vv.y, h01, l01);
        split_pack(vv.z, vv.w, h23, l23);
        *(uint32_t*)(smc + VH_OFF + off)     = h01;
        *(uint32_t*)(smc + VH_OFF + off + 4) = h23;
        *(uint32_t*)(smc + VL_OFF + off)     = l01;
        *(uint32_t*)(smc + VL_OFF + off + 4) = l23;
    }
    // ---- stage S (hi/lo) ----
    {
        const float* Sg = g_S[tile];
        for (int p = tid; p < EDIM * DDIM; p += 256) {
            const int e = p >> 6;
            const int d = p & 63;
            __nv_bfloat16 hh, ll;
            split1(Sg[p], hh, ll);
            *(__nv_bfloat16*)(smc + SH_OFF + (e * QS + d) * 2) = hh;
            *(__nv_bfloat16*)(smc + SL_OFF + (e * QS + d) * 2) = ll;
        }
    }
    __syncthreads();

    const int m0  = wid * 16;
    const int gi  = lid & 7;
    const int grp = lid >> 3;

    // ---- MMA1: scores[128,128] = Qf @ Kf^T (k = 64) ----
    {
        float C[16][4] = {};
        for (int kk = 0; kk < EDIM; kk += 16) {
            uint32_t ah[4], al[4];
            const int arow = m0 + ((grp & 1) ? 8 : 0) + gi;
            const int acol = kk + ((grp & 2) ? 8 : 0);
            const uint32_t aoff = (uint32_t)(arow * QS + acol) * 2;
            ldsm_x4(ah, smb + QH_OFF + aoff);
            ldsm_x4(al, smb + QL_OFF + aoff);
            const int bcol = kk + ((grp & 1) ? 8 : 0);
            #pragma unroll
            for (int nt = 0; nt < 16; nt++) {
                const uint32_t boff = (uint32_t)((nt * 8 + gi) * QS + bcol) * 2;
                uint32_t bh[2], bl[2];
                ldsm_x2(bh, smb + KH_OFF + boff);
                ldsm_x2(bl, smb + KL_OFF + boff);
                mma16816(C[nt], ah, bh);
                mma16816(C[nt], ah, bl);
                mma16816(C[nt], al, bh);
            }
        }

        // mask tril, rowsum, split -> score planes
        const int r0 = m0 + (lid >> 2);
        const int r1 = r0 + 8;
        float rs0 = 0.f, rs1 = 0.f;
        #pragma unroll
        for (int nt = 0; nt < 16; nt++) {
            const int cb = nt * 8 + (lid & 3) * 2;
            float c0 = (cb     <= r0) ? C[nt][0] : 0.f;
            float c1 = (cb + 1 <= r0) ? C[nt][1] : 0.f;
            float c2 = (cb     <= r1) ? C[nt][2] : 0.f;
            float c3 = (cb + 1 <= r1) ? C[nt][3] : 0.f;
            rs0 += c0 + c1;
            rs1 += c2 + c3;
            uint32_t hi, lo;
            split_pack(c0, c1, hi, lo);
            *(uint32_t*)(smc + SCH_OFF + (r0 * SCS + cb) * 2) = hi;
            *(uint32_t*)(smc + SCL_OFF + (r0 * SCS + cb) * 2) = lo;
            split_pack(c2, c3, hi, lo);
            *(uint32_t*)(smc + SCH_OFF + (r1 * SCS + cb) * 2) = hi;
            *(uint32_t*)(smc + SCL_OFF + (r1 * SCS + cb) * 2) = lo;
        }
        rs0 += __shfl_xor_sync(0xffffffffu, rs0, 1);
        rs0 += __shfl_xor_sync(0xffffffffu, rs0, 2);
        rs1 += __shfl_xor_sync(0xffffffffu, rs1, 1);
        rs1 += __shfl_xor_sync(0xffffffffu, rs1, 2);
        if ((lid & 3) == 0) { dnm[r0] = rs0; dnm[r1] = rs1; }
    }
    __syncthreads();

    // ---- denominator: 1 / (rowsum + qf.ksum + eps) ----
    if (tid < CHK) {
        float s = dnm[tid];
        #pragma unroll 8
        for (int e = 0; e < EDIM; e++) {
            const float qv =
                __bfloat162float(*(const __nv_bfloat16*)(smc + QH_OFF + (tid * QS + e) * 2)) +
                __bfloat162float(*(const __nv_bfloat16*)(smc + QL_OFF + (tid * QS + e) * 2));
            s = fmaf(qv, ksum[e], s);
        }
        dnm[tid] = 1.f / (s + 1e-6f);
    }

    // ---- MMA2: out = scores @ V (k=128);  MMA3: out += Qf @ S (k=64) ----
    float C2[8][4] = {};
    for (int kk = 0; kk < CHK; kk += 16) {
        uint32_t ah[4], al[4];
        const int arow = m0 + ((grp & 1) ? 8 : 0) + gi;
        const int acol = kk + ((grp & 2) ? 8 : 0);
        const uint32_t aoff = (uint32_t)(arow * SCS + acol) * 2;
        ldsm_x4(ah, smb + SCH_OFF + aoff);
        ldsm_x4(al, smb + SCL_OFF + aoff);
        const int brow = kk + ((grp & 1) ? 8 : 0) + gi;
        #pragma unroll
        for (int nt = 0; nt < 8; nt++) {
            const uint32_t boff = (uint32_t)(brow * QS + nt * 8) * 2;
            uint32_t bh[2], bl[2];
            ldsm_x2t(bh, smb + VH_OFF + boff);
            ldsm_x2t(bl, smb + VL_OFF + boff);
            mma16816(C2[nt], ah, bh);
            mma16816(C2[nt], ah, bl);
            mma16816(C2[nt], al, bh);
        }
    }
    for (int kk = 0; kk < EDIM; kk += 16) {
        uint32_t ah[4], al[4];
        const int arow = m0 + ((grp & 1) ? 8 : 0) + gi;
        const int acol = kk + ((grp & 2) ? 8 : 0);
        const uint32_t aoff = (uint32_t)(arow * QS + acol) * 2;
        ldsm_x4(ah, smb + QH_OFF + aoff);
        ldsm_x4(al, smb + QL_OFF + aoff);
        const int brow = kk + ((grp & 1) ? 8 : 0) + gi;
        #pragma unroll
        for (int nt = 0; nt < 8; nt++) {
            const uint32_t boff = (uint32_t)(brow * QS + nt * 8) * 2;
            uint32_t bh[2], bl[2];
            ldsm_x2t(bh, smb + SH_OFF + boff);
            ldsm_x2t(bl, smb + SL_OFF + boff);
            mma16816(C2[nt], ah, bh);
            mma16816(C2[nt], ah, bl);
            mma16816(C2[nt], al, bh);
        }
    }
    __syncthreads();   // scores consumed + dnm final -> safe to reuse SCH as outb

    // ---- epilogue: scale by dnm -> smem -> coalesced STG ----
    {
        const int r0 = m0 + (lid >> 2);
        const int r1 = r0 + 8;
        const float z0 = dnm[r0];
        const float z1 = dnm[r1];
        #pragma unroll
        for (int nt = 0; nt < 8; nt++) {
            const int cb = nt * 8 + (lid & 3) * 2;
            outb[r0 * 68 + cb]     = C2[nt][0] * z0;
            outb[r0 * 68 + cb + 1] = C2[nt][1] * z0;
            outb[r1 * 68 + cb]     = C2[nt][2] * z1;
            outb[r1 * 68 + cb + 1] = C2[nt][3] * z1;
        }
    }
    __syncthreads();

    const size_t obase = (((size_t)n * LSEQ + (size_t)c * CHK) * HEADS + h) * DDIM;
    for (int p = tid; p < CHK * 16; p += 256) {
        const int row = p >> 4;
        const int c4  = (p & 15) << 2;
        const float4 v4 = *(const float4*)(outb + row * 68 + c4);
        *(float4*)(out + obase + (size_t)row * ROWSTR + c4) = v4;
    }
}

// ---------------------------------------------------------------------------
extern "C" void kernel_launch(void* const* d_in, const int* in_sizes, int n_in,
                              void* d_out, int out_size) {
    const float* Q = (const float*)d_in[0];
    const float* K = (const float*)d_in[1];
    const float* V = (const float*)d_in[2];
    float* out = (float*)d_out;

    cudaFuncSetAttribute(k_pass1, cudaFuncAttributeMaxDynamicSharedMemorySize, P1_SMEM);
    cudaFuncSetAttribute(k_pass3, cudaFuncAttributeMaxDynamicSharedMemorySize, P3_SMEM);

    k_pass1<<<NTILE, 128, P1_SMEM>>>(K, V);
    k_pass2<<<dim3(16, 64), 256>>>();
    k_pass3<<<NTILE, 256, P3_SMEM>>>(Q, K, V, out);
}

// round 4
// speedup vs baseline: 3.3089x; 1.9724x over previous
#include <cuda_runtime.h>
#include <cuda_bf16.h>
#include <cstdint>

// Problem constants (fixed shapes)
#define NBATCH 4
#define LSEQ   8192
#define HEADS  16
#define EDIM   64
#define DDIM   64
#define CHK    128
#define NCH    64
#define NTILE  (NBATCH*HEADS*NCH)      // 4096
#define ROWSTR (HEADS*EDIM)            // 1024

__device__ float g_S [NTILE][EDIM*DDIM];   // 64 MB
__device__ float g_ks[NTILE][EDIM];        // 1 MB

__device__ __forceinline__ float featmap(float x) {
    return x > 0.f ? x + 1.f : __expf(x);
}
__device__ __forceinline__ uint32_t smem_u32(const void* p) {
    return (uint32_t)__cvta_generic_to_shared(p);
}
// SW128 xor swizzle on byte offsets within a plane of 128B rows
__device__ __forceinline__ uint32_t sw(uint32_t x) { return x ^ ((x >> 3) & 0x70); }

// ---- warp-level tensor core primitives --------------------------------------
__device__ __forceinline__ void mma16816(float* c, const uint32_t* a, const uint32_t* b) {
    asm volatile(
        "mma.sync.aligned.m16n8k16.row.col.f32.bf16.bf16.f32 "
        "{%0,%1,%2,%3}, {%4,%5,%6,%7}, {%8,%9}, {%0,%1,%2,%3};"
        : "+f"(c[0]), "+f"(c[1]), "+f"(c[2]), "+f"(c[3])
        : "r"(a[0]), "r"(a[1]), "r"(a[2]), "r"(a[3]), "r"(b[0]), "r"(b[1]));
}
__device__ __forceinline__ void ldsm_x4(uint32_t* r, uint32_t addr) {
    asm volatile("ldmatrix.sync.aligned.m8n8.x4.shared.b16 {%0,%1,%2,%3}, [%4];"
                 : "=r"(r[0]), "=r"(r[1]), "=r"(r[2]), "=r"(r[3]) : "r"(addr));
}
__device__ __forceinline__ void ldsm_x4t(uint32_t* r, uint32_t addr) {
    asm volatile("ldmatrix.sync.aligned.m8n8.x4.trans.shared.b16 {%0,%1,%2,%3}, [%4];"
                 : "=r"(r[0]), "=r"(r[1]), "=r"(r[2]), "=r"(r[3]) : "r"(addr));
}
__device__ __forceinline__ void ldsm_x2(uint32_t* r, uint32_t addr) {
    asm volatile("ldmatrix.sync.aligned.m8n8.x2.shared.b16 {%0,%1}, [%2];"
                 : "=r"(r[0]), "=r"(r[1]) : "r"(addr));
}
__device__ __forceinline__ void ldsm_x2t(uint32_t* r, uint32_t addr) {
    asm volatile("ldmatrix.sync.aligned.m8n8.x2.trans.shared.b16 {%0,%1}, [%2];"
                 : "=r"(r[0]), "=r"(r[1]) : "r"(addr));
}

__device__ __forceinline__ void split_pack(float a, float b, uint32_t& hi, uint32_t& lo) {
    __nv_bfloat16 ah = __float2bfloat16(a), bh = __float2bfloat16(b);
    __nv_bfloat16 al = __float2bfloat16(a - __bfloat162float(ah));
    __nv_bfloat16 bl = __float2bfloat16(b - __bfloat162float(bh));
    hi = ((uint32_t)__bfloat16_as_ushort(bh) << 16) | (uint32_t)__bfloat16_as_ushort(ah);
    lo = ((uint32_t)__bfloat16_as_ushort(bl) << 16) | (uint32_t)__bfloat16_as_ushort(al);
}
__device__ __forceinline__ void split1(float a, __nv_bfloat16& hi, __nv_bfloat16& lo) {
    hi = __float2bfloat16(a);
    lo = __float2bfloat16(a - __bfloat162float(hi));
}

// ---------------------------------------------------------------------------
// Pass 1: S_c = phi(K)^T V  (64x64, k=128) ; ksum_c.   block=256, grid=4096
// ---------------------------------------------------------------------------
#define P1_KH 0
#define P1_KL 16384
#define P1_VH 32768
#define P1_VL 49152
#define P1_KS 65536
#define P1_SMEM (P1_KS + 256)

__global__ void __launch_bounds__(256) k_pass1(const float* __restrict__ keys,
                                               const float* __restrict__ values) {
    extern __shared__ char smc[];
    const uint32_t smb = smem_u32(smc);
    float* ksum = (float*)(smc + P1_KS);

    const int tile = blockIdx.x;
    const int c  = tile & (NCH - 1);
    const int nh = tile >> 6;
    const int h  = nh & (HEADS - 1);
    const int n  = nh >> 4;
    const int tid = threadIdx.x;
    const int wid = tid >> 5;
    const int lid = tid & 31;

    if (tid < EDIM) ksum[tid] = 0.f;
    __syncthreads();

    const size_t base = (((size_t)n * LSEQ + (size_t)c * CHK) * HEADS + h) * EDIM;

    float ksr[4] = {0.f, 0.f, 0.f, 0.f};
    const int c4 = (tid & 15) << 2;           // column group fixed per thread
    #pragma unroll
    for (int i = 0; i < 8; i++) {
        const int p   = tid + i * 256;
        const int row = p >> 4;
        const size_t g = base + (size_t)row * ROWSTR + c4;
        const float4 kv = *(const float4*)(keys   + g);
        const float4 vv = *(const float4*)(values + g);
        const float kf[4] = {featmap(kv.x), featmap(kv.y), featmap(kv.z), featmap(kv.w)};
        #pragma unroll
        for (int j = 0; j < 4; j++) ksr[j] += kf[j];

        const uint32_t x = sw((uint32_t)(row * 128 + c4 * 2));
        uint32_t h01, l01, h23, l23;
        split_pack(kf[0], kf[1], h01, l01);
        split_pack(kf[2], kf[3], h23, l23);
        *(uint2*)(smc + P1_KH + x) = make_uint2(h01, h23);
        *(uint2*)(smc + P1_KL + x) = make_uint2(l01, l23);
        split_pack(vv.x, vv.y, h01, l01);
        split_pack(vv.z, vv.w, h23, l23);
        *(uint2*)(smc + P1_VH + x) = make_uint2(h01, h23);
        *(uint2*)(smc + P1_VL + x) = make_uint2(l01, l23);
    }
    #pragma unroll
    for (int j = 0; j < 4; j++) atomicAdd(&ksum[c4 + j], ksr[j]);
    __syncthreads();

    if (tid < EDIM) g_ks[tile][tid] = ksum[tid];

    // MMA: warp wid computes S rows mrow..mrow+15, cols nhalf..nhalf+31
    const int mrow  = (wid & 3) * 16;
    const int nhalf = (wid >> 2) * 32;
    const int gi  = lid & 7;
    const int grp = lid >> 3;
    float C[4][4] = {};
    for (int kk = 0; kk < CHK; kk += 16) {
        uint32_t ah[4], al[4];
        const int arow = kk + ((grp & 2) ? 8 : 0) + gi;
        const int acol = mrow + ((grp & 1) ? 8 : 0);
        const uint32_t ax = sw((uint32_t)(arow * 128 + acol * 2));
        ldsm_x4t(ah, smb + P1_KH + ax);
        ldsm_x4t(al, smb + P1_KL + ax);
        const int brow = kk + ((grp & 1) ? 8 : 0) + gi;
        #pragma unroll
        for (int nt = 0; nt < 4; nt++) {
            const uint32_t bx = sw((uint32_t)(brow * 128 + (nhalf + nt * 8) * 2));
            uint32_t bh[2], bl[2];
            ldsm_x2t(bh, smb + P1_VH + bx);
            ldsm_x2t(bl, smb + P1_VL + bx);
            mma16816(C[nt], ah, bh);
            mma16816(C[nt], ah, bl);
            mma16816(C[nt], al, bh);
        }
    }
    float* So = g_S[tile];
    const int e0 = mrow + (lid >> 2);
    const int e1 = e0 + 8;
    #pragma unroll
    for (int nt = 0; nt < 4; nt++) {
        const int d = nhalf + nt * 8 + (lid & 3) * 2;
        *(float2*)(So + e0 * 64 + d) = make_float2(C[nt][0], C[nt][1]);
        *(float2*)(So + e1 * 64 + d) = make_float2(C[nt][2], C[nt][3]);
    }
}

// ---------------------------------------------------------------------------
// Pass 2: exclusive prefix over chunks. grid=(16,64), block=256
// ---------------------------------------------------------------------------
__global__ void __launch_bounds__(256) k_pass2() {
    const int nh  = blockIdx.y;
    const int idx = blockIdx.x * 256 + threadIdx.x;
    const int base = nh * NCH;

    float run = 0.f;
    #pragma unroll 4
    for (int c = 0; c < NCH; c++) {
        const float t = g_S[base + c][idx];
        g_S[base + c][idx] = run;
        run += t;
    }
    if (blockIdx.x == 0 && threadIdx.x < EDIM) {
        const int e = threadIdx.x;
        float kr = 0.f;
        #pragma unroll 4
        for (int c = 0; c < NCH; c++) {
            const float t = g_ks[base + c][e];
            g_ks[base + c][e] = kr;
            kr += t;
        }
    }
}

// ---------------------------------------------------------------------------
// Pass 3: out = (Qf@S + tril(Qf Kf^T)@V) / (Qf.ksum + rowsum)
// block=256 (8 warps), 2 CTAs/SM. Scores never leave registers.
// ---------------------------------------------------------------------------
#define QH_OFF   0
#define QL_OFF   16384
#define KH_OFF   32768
#define KL_OFF   49152
#define VH_OFF   65536
#define VL_OFF   81920
#define SH_OFF   98304
#define SL_OFF   106496
#define KSUM_OFF 114688
#define DNM_OFF  114944
#define P3_SMEM  115456
#define OUTB_OFF 0          // reuse Q/K planes for f32 [128][68] staging

__global__ void __launch_bounds__(256, 2) k_pass3(const float* __restrict__ Qg,
                                                  const float* __restrict__ Kg,
                                                  const float* __restrict__ Vg,
                                                  float* __restrict__ out) {
    extern __shared__ char smc[];
    const uint32_t smb = smem_u32(smc);
    float* ksum = (float*)(smc + KSUM_OFF);
    float* dnm  = (float*)(smc + DNM_OFF);
    float* outb = (float*)(smc + OUTB_OFF);

    const int tile = blockIdx.x;
    const int c  = tile & (NCH - 1);
    const int nh = tile >> 6;
    const int h  = nh & (HEADS - 1);
    const int n  = nh >> 4;
    const int tid = threadIdx.x;
    const int wid = tid >> 5;
    const int lid = tid & 31;

    if (tid < EDIM) ksum[tid] = g_ks[tile][tid];
    if (tid < CHK)  dnm[tid] = 0.f;
    __syncthreads();

    const size_t base = (((size_t)n * LSEQ + (size_t)c * CHK) * HEADS + h) * EDIM;

    // ---- stage Q,K (featmap, hi/lo, swizzled) + V; fuse q.ksum partials ----
    {
        const int c4 = (tid & 15) << 2;
        #pragma unroll
        for (int i = 0; i < 8; i++) {
            const int p   = tid + i * 256;
            const int row = p >> 4;
            const size_t g = base + (size_t)row * ROWSTR + c4;
            const float4 qv = *(const float4*)(Qg + g);
            const float4 kv = *(const float4*)(Kg + g);
            const float4 vv = *(const float4*)(Vg + g);
            const float qf[4] = {featmap(qv.x), featmap(qv.y), featmap(qv.z), featmap(qv.w)};
            float part = qf[0] * ksum[c4] + qf[1] * ksum[c4 + 1]
                       + qf[2] * ksum[c4 + 2] + qf[3] * ksum[c4 + 3];
            atomicAdd(&dnm[row], part);

            const uint32_t x = sw((uint32_t)(row * 128 + c4 * 2));
            uint32_t h01, l01, h23, l23;
            split_pack(qf[0], qf[1], h01, l01);
            split_pack(qf[2], qf[3], h23, l23);
            *(uint2*)(smc + QH_OFF + x) = make_uint2(h01, h23);
            *(uint2*)(smc + QL_OFF + x) = make_uint2(l01, l23);
            split_pack(featmap(kv.x), featmap(kv.y), h01, l01);
            split_pack(featmap(kv.z), featmap(kv.w), h23, l23);
            *(uint2*)(smc + KH_OFF + x) = make_uint2(h01, h23);
            *(uint2*)(smc + KL_OFF + x) = make_uint2(l01, l23);
            split_pack(vv.x, vv.y, h01, l01);
            split_pack(vv.z, vv.w, h23, l23);
            *(uint2*)(smc + VH_OFF + x) = make_uint2(h01, h23);
            *(uint2*)(smc + VL_OFF + x) = make_uint2(l01, l23);
        }
    }
    // ---- stage S (hi/lo, swizzled) ----
    {
        const float* Sg = g_S[tile];
        #pragma unroll
        for (int i = 0; i < 8; i++) {
            const int idx = (tid + i * 256) * 2;
            const int e = idx >> 6;
            const int d = idx & 63;
            const float2 s2 = *(const float2*)(Sg + idx);
            __nv_bfloat16 h0, l0, h1, l1;
            split1(s2.x, h0, l0);
            split1(s2.y, h1, l1);
            const uint32_t x = sw((uint32_t)(e * 128 + d * 2));
            *(uint32_t*)(smc + SH_OFF + x) =
                ((uint32_t)__bfloat16_as_ushort(h1) << 16) | __bfloat16_as_ushort(h0);
            *(uint32_t*)(smc + SL_OFF + x) =
                ((uint32_t)__bfloat16_as_ushort(l1) << 16) | __bfloat16_as_ushort(l0);
        }
    }
    __syncthreads();

    const int m0  = wid * 16;
    const int gi  = lid & 7;
    const int grp = lid >> 3;
    const int r0f = lid >> 2;          // fragment row within 16
    const int r0  = m0 + r0f;
    const int r1  = r0 + 8;

    // ---- MMA1: scores (kept in registers) ----
    float C[16][4] = {};
    for (int kk = 0; kk < EDIM; kk += 16) {
        uint32_t ah[4], al[4];
        const int arow = m0 + ((grp & 1) ? 8 : 0) + gi;
        const int acol = kk + ((grp & 2) ? 8 : 0);
        const uint32_t ax = sw((uint32_t)(arow * 128 + acol * 2));
        ldsm_x4(ah, smb + QH_OFF + ax);
        ldsm_x4(al, smb + QL_OFF + ax);
        const int bcol = kk + ((grp & 1) ? 8 : 0);
        #pragma unroll
        for (int nt = 0; nt < 16; nt++) {
            const uint32_t bx = sw((uint32_t)((nt * 8 + gi) * 128 + bcol * 2));
            uint32_t bh[2], bl[2];
            ldsm_x2(bh, smb + KH_OFF + bx);
            ldsm_x2(bl, smb + KL_OFF + bx);
            mma16816(C[nt], ah, bh);
            mma16816(C[nt], ah, bl);
            mma16816(C[nt], al, bh);
        }
    }

    // ---- mask + rowsum + feed scores straight into MMA2 from registers ----
    float C2[8][4] = {};
    float rs0 = 0.f, rs1 = 0.f;
    #pragma unroll
    for (int j = 0; j < 8; j++) {
        const int cA = j * 16 + (lid & 3) * 2;      // cols of C[2j]
        const int cB = cA + 8;                      // cols of C[2j+1]
        float s00 = (cA     <= r0) ? C[2*j][0]   : 0.f;
        float s01 = (cA + 1 <= r0) ? C[2*j][1]   : 0.f;
        float s02 = (cA     <= r1) ? C[2*j][2]   : 0.f;
        float s03 = (cA + 1 <= r1) ? C[2*j][3]   : 0.f;
        float s10 = (cB     <= r0) ? C[2*j+1][0] : 0.f;
        float s11 = (cB + 1 <= r0) ? C[2*j+1][1] : 0.f;
        float s12 = (cB     <= r1) ? C[2*j+1][2] : 0.f;
        float s13 = (cB + 1 <= r1) ? C[2*j+1][3] : 0.f;
        rs0 += s00 + s01 + s10 + s11;
        rs1 += s02 + s03 + s12 + s13;
        uint32_t ah[4], al[4];
        split_pack(s00, s01, ah[0], al[0]);
        split_pack(s02, s03, ah[1], al[1]);
        split_pack(s10, s11, ah[2], al[2]);
        split_pack(s12, s13, ah[3], al[3]);
        const int brow = j * 16 + ((grp & 1) ? 8 : 0) + gi;
        #pragma unroll
        for (int nt = 0; nt < 8; nt++) {
            const uint32_t bx = sw((uint32_t)(brow * 128 + nt * 16));
            uint32_t bh[2], bl[2];
            ldsm_x2t(bh, smb + VH_OFF + bx);
            ldsm_x2t(bl, smb + VL_OFF + bx);
            mma16816(C2[nt], ah, bh);
            mma16816(C2[nt], ah, bl);
            mma16816(C2[nt], al, bh);
        }
    }
    rs0 += __shfl_xor_sync(0xffffffffu, rs0, 1);
    rs0 += __shfl_xor_sync(0xffffffffu, rs0, 2);
    rs1 += __shfl_xor_sync(0xffffffffu, rs1, 1);
    rs1 += __shfl_xor_sync(0xffffffffu, rs1, 2);
    if ((lid & 3) == 0) {
        atomicAdd(&dnm[r0], rs0);
        atomicAdd(&dnm[r1], rs1);
    }

    // ---- MMA3: C2 += Qf @ S ----
    for (int kk = 0; kk < EDIM; kk += 16) {
        uint32_t ah[4], al[4];
        const int arow = m0 + ((grp & 1) ? 8 : 0) + gi;
        const int acol = kk + ((grp & 2) ? 8 : 0);
        const uint32_t ax = sw((uint32_t)(arow * 128 + acol * 2));
        ldsm_x4(ah, smb + QH_OFF + ax);
        ldsm_x4(al, smb + QL_OFF + ax);
        const int brow = kk + ((grp & 1) ? 8 : 0) + gi;
        #pragma unroll
        for (int nt = 0; nt < 8; nt++) {
            const uint32_t bx = sw((uint32_t)(brow * 128 + nt * 16));
            uint32_t bh[2], bl[2];
            ldsm_x2t(bh, smb + SH_OFF + bx);
            ldsm_x2t(bl, smb + SL_OFF + bx);
            mma16816(C2[nt], ah, bh);
            mma16816(C2[nt], ah, bl);
            mma16816(C2[nt], al, bh);
        }
    }
    __syncthreads();
    if (tid < CHK) dnm[tid] = 1.f / (dnm[tid] + 1e-6f);
    __syncthreads();

    // ---- epilogue: scale, stage (over dead Q/K planes), coalesced STG ----
    {
        const float z0 = dnm[r0];
        const float z1 = dnm[r1];
        #pragma unroll
        for (int nt = 0; nt < 8; nt++) {
            const int cb = nt * 8 + (lid & 3) * 2;
            outb[r0 * 68 + cb]     = C2[nt][0] * z0;
            outb[r0 * 68 + cb + 1] = C2[nt][1] * z0;
            outb[r1 * 68 + cb]     = C2[nt][2] * z1;
            outb[r1 * 68 + cb + 1] = C2[nt][3] * z1;
        }
    }
    __syncthreads();

    const size_t obase = (((size_t)n * LSEQ + (size_t)c * CHK) * HEADS + h) * DDIM;
    {
        const int c4 = (tid & 15) << 2;
        #pragma unroll
        for (int i = 0; i < 8; i++) {
            const int p   = tid + i * 256;
            const int row = p >> 4;
            const float4 v4 = *(const float4*)(outb + row * 68 + c4);
            *(float4*)(out + obase + (size_t)row * ROWSTR + c4) = v4;
        }
    }
}

// ---------------------------------------------------------------------------
extern "C" void kernel_launch(void* const* d_in, const int* in_sizes, int n_in,
                              void* d_out, int out_size) {
    const float* Q = (const float*)d_in[0];
    const float* K = (const float*)d_in[1];
    const float* V = (const float*)d_in[2];
    float* out = (float*)d_out;

    cudaFuncSetAttribute(k_pass1, cudaFuncAttributeMaxDynamicSharedMemorySize, P1_SMEM);
    cudaFuncSetAttribute(k_pass3, cudaFuncAttributeMaxDynamicSharedMemorySize, P3_SMEM);

    k_pass1<<<NTILE, 256, P1_SMEM>>>(K, V);
    k_pass2<<<dim3(16, 64), 256>>>();
    k_pass3<<<NTILE, 256, P3_SMEM>>>(Q, K, V, out);
}

// round 5
// speedup vs baseline: 3.6270x; 1.0961x over previous
#include <cuda_runtime.h>
#include <cuda_bf16.h>
#include <cstdint>

// Problem constants (fixed shapes)
#define NBATCH 4
#define LSEQ   8192
#define HEADS  16
#define EDIM   64
#define DDIM   64
#define CHK    128
#define NCH    64
#define NTILE  (NBATCH*HEADS*NCH)      // 4096
#define ROWSTR (HEADS*EDIM)            // 1024

__device__ float g_S [NTILE][EDIM*DDIM];   // 64 MB
__device__ float g_ks[NTILE][EDIM];        // 1 MB

__device__ __forceinline__ float featmap(float x) {
    return x > 0.f ? x + 1.f : __expf(x);
}
__device__ __forceinline__ uint32_t smem_u32(const void* p) {
    return (uint32_t)__cvta_generic_to_shared(p);
}
__device__ __forceinline__ uint32_t sw(uint32_t x) { return x ^ ((x >> 3) & 0x70); }

// ---- warp-level tensor core primitives --------------------------------------
__device__ __forceinline__ void mma16816(float* c, const uint32_t* a, const uint32_t* b) {
    asm volatile(
        "mma.sync.aligned.m16n8k16.row.col.f32.bf16.bf16.f32 "
        "{%0,%1,%2,%3}, {%4,%5,%6,%7}, {%8,%9}, {%0,%1,%2,%3};"
        : "+f"(c[0]), "+f"(c[1]), "+f"(c[2]), "+f"(c[3])
        : "r"(a[0]), "r"(a[1]), "r"(a[2]), "r"(a[3]), "r"(b[0]), "r"(b[1]));
}
__device__ __forceinline__ void ldsm_x4(uint32_t* r, uint32_t addr) {
    asm volatile("ldmatrix.sync.aligned.m8n8.x4.shared.b16 {%0,%1,%2,%3}, [%4];"
                 : "=r"(r[0]), "=r"(r[1]), "=r"(r[2]), "=r"(r[3]) : "r"(addr));
}
__device__ __forceinline__ void ldsm_x4t(uint32_t* r, uint32_t addr) {
    asm volatile("ldmatrix.sync.aligned.m8n8.x4.trans.shared.b16 {%0,%1,%2,%3}, [%4];"
                 : "=r"(r[0]), "=r"(r[1]), "=r"(r[2]), "=r"(r[3]) : "r"(addr));
}

__device__ __forceinline__ void split_pack(float a, float b, uint32_t& hi, uint32_t& lo) {
    __nv_bfloat16 ah = __float2bfloat16(a), bh = __float2bfloat16(b);
    __nv_bfloat16 al = __float2bfloat16(a - __bfloat162float(ah));
    __nv_bfloat16 bl = __float2bfloat16(b - __bfloat162float(bh));
    hi = ((uint32_t)__bfloat16_as_ushort(bh) << 16) | (uint32_t)__bfloat16_as_ushort(ah);
    lo = ((uint32_t)__bfloat16_as_ushort(bl) << 16) | (uint32_t)__bfloat16_as_ushort(al);
}
__device__ __forceinline__ void split1(float a, __nv_bfloat16& hi, __nv_bfloat16& lo) {
    hi = __float2bfloat16(a);
    lo = __float2bfloat16(a - __bfloat162float(hi));
}

// ---------------------------------------------------------------------------
// Pass 1: S_c = phi(K)^T V  (64x64, k=128) ; ksum_c.   block=256, grid=4096
// ---------------------------------------------------------------------------
#define P1_KH 0
#define P1_KL 16384
#define P1_VH 32768
#define P1_VL 49152
#define P1_KS 65536
#define P1_SMEM (P1_KS + 256)

__global__ void __launch_bounds__(256) k_pass1(const float* __restrict__ keys,
                                               const float* __restrict__ values) {
    extern __shared__ char smc[];
    const uint32_t smb = smem_u32(smc);
    float* ksum = (float*)(smc + P1_KS);

    const int tile = blockIdx.x;
    const int c  = tile & (NCH - 1);
    const int nh = tile >> 6;
    const int h  = nh & (HEADS - 1);
    const int n  = nh >> 4;
    const int tid = threadIdx.x;
    const int wid = tid >> 5;
    const int lid = tid & 31;

    if (tid < EDIM) ksum[tid] = 0.f;
    __syncthreads();

    const size_t base = (((size_t)n * LSEQ + (size_t)c * CHK) * HEADS + h) * EDIM;

    float ksr[4] = {0.f, 0.f, 0.f, 0.f};
    const int c4 = (tid & 15) << 2;
    #pragma unroll
    for (int i = 0; i < 8; i++) {
        const int p   = tid + i * 256;
        const int row = p >> 4;
        const size_t g = base + (size_t)row * ROWSTR + c4;
        const float4 kv = *(const float4*)(keys   + g);
        const float4 vv = *(const float4*)(values + g);
        const float kf[4] = {featmap(kv.x), featmap(kv.y), featmap(kv.z), featmap(kv.w)};
        #pragma unroll
        for (int j = 0; j < 4; j++) ksr[j] += kf[j];

        const uint32_t x = sw((uint32_t)(row * 128 + c4 * 2));
        uint32_t h01, l01, h23, l23;
        split_pack(kf[0], kf[1], h01, l01);
        split_pack(kf[2], kf[3], h23, l23);
        *(uint2*)(smc + P1_KH + x) = make_uint2(h01, h23);
        *(uint2*)(smc + P1_KL + x) = make_uint2(l01, l23);
        split_pack(vv.x, vv.y, h01, l01);
        split_pack(vv.z, vv.w, h23, l23);
        *(uint2*)(smc + P1_VH + x) = make_uint2(h01, h23);
        *(uint2*)(smc + P1_VL + x) = make_uint2(l01, l23);
    }
    #pragma unroll
    for (int j = 0; j < 4; j++) atomicAdd(&ksum[c4 + j], ksr[j]);
    __syncthreads();

    if (tid < EDIM) g_ks[tile][tid] = ksum[tid];

    const int mrow  = (wid & 3) * 16;
    const int nhalf = (wid >> 2) * 32;
    const int gi  = lid & 7;
    const int grp = lid >> 3;
    const int g1  = grp & 1;
    const int q2  = grp >> 1;
    float C[4][4] = {};
    for (int kk = 0; kk < CHK; kk += 16) {
        uint32_t ah[4], al[4];
        const int arow = kk + ((grp & 2) ? 8 : 0) + gi;
        const int acol = mrow + ((grp & 1) ? 8 : 0);
        const uint32_t ax = sw((uint32_t)(arow * 128 + acol * 2));
        ldsm_x4t(ah, smb + P1_KH + ax);
        ldsm_x4t(al, smb + P1_KL + ax);
        const int brow = kk + g1 * 8 + gi;
        #pragma unroll
        for (int nt = 0; nt < 4; nt += 2) {
            const uint32_t bx = sw((uint32_t)(brow * 128 + (nhalf + (nt + q2) * 8) * 2));
            uint32_t bh[4], bl[4];
            ldsm_x4t(bh, smb + P1_VH + bx);
            ldsm_x4t(bl, smb + P1_VL + bx);
            mma16816(C[nt], ah, bh);
            mma16816(C[nt], ah, bl);
            mma16816(C[nt], al, bh);
            mma16816(C[nt+1], ah, bh + 2);
            mma16816(C[nt+1], ah, bl + 2);
            mma16816(C[nt+1], al, bh + 2);
        }
    }
    float* So = g_S[tile];
    const int e0 = mrow + (lid >> 2);
    const int e1 = e0 + 8;
    #pragma unroll
    for (int nt = 0; nt < 4; nt++) {
        const int d = nhalf + nt * 8 + (lid & 3) * 2;
        *(float2*)(So + e0 * 64 + d) = make_float2(C[nt][0], C[nt][1]);
        *(float2*)(So + e1 * 64 + d) = make_float2(C[nt][2], C[nt][3]);
    }
}

// ---------------------------------------------------------------------------
// Pass 2: exclusive prefix over chunks, float4 per thread. grid=(4,64)
// ---------------------------------------------------------------------------
__global__ void __launch_bounds__(256) k_pass2() {
    const int nh  = blockIdx.y;
    const int idx = (blockIdx.x * 256 + threadIdx.x) * 4;
    const int base = nh * NCH;

    float4 run = make_float4(0.f, 0.f, 0.f, 0.f);
    #pragma unroll 4
    for (int c = 0; c < NCH; c++) {
        float4* p = (float4*)&g_S[base + c][idx];
        const float4 t = *p;
        *p = run;
        run.x += t.x; run.y += t.y; run.z += t.z; run.w += t.w;
    }
    if (blockIdx.x == 0 && threadIdx.x < EDIM) {
        const int e = threadIdx.x;
        float kr = 0.f;
        #pragma unroll 4
        for (int c = 0; c < NCH; c++) {
            const float t = g_ks[base + c][e];
            g_ks[base + c][e] = kr;
            kr += t;
        }
    }
}

// ---------------------------------------------------------------------------
// Pass 3: out = (Qf@S + tril(Qf Kf^T)@V) / (Qf.ksum + rowsum)
// block=256 (8 warps), 2 CTAs/SM. Scores streamed in two 64-col halves.
// ---------------------------------------------------------------------------
#define QH_OFF   0
#define QL_OFF   16384
#define KH_OFF   32768
#define KL_OFF   49152
#define VH_OFF   65536
#define VL_OFF   81920
#define SH_OFF   98304
#define SL_OFF   106496
#define KSUM_OFF 114688
#define DNM_OFF  114944
#define P3_SMEM  115456
#define OUTB_OFF 0          // reuse Q/K planes for f32 [128][68] staging

__global__ void __launch_bounds__(256, 2) k_pass3(const float* __restrict__ Qg,
                                                  const float* __restrict__ Kg,
                                                  const float* __restrict__ Vg,
                                                  float* __restrict__ out) {
    extern __shared__ char smc[];
    const uint32_t smb = smem_u32(smc);
    float* ksum = (float*)(smc + KSUM_OFF);
    float* dnm  = (float*)(smc + DNM_OFF);
    float* outb = (float*)(smc + OUTB_OFF);

    const int tile = blockIdx.x;
    const int c  = tile & (NCH - 1);
    const int nh = tile >> 6;
    const int h  = nh & (HEADS - 1);
    const int n  = nh >> 4;
    const int tid = threadIdx.x;
    const int wid = tid >> 5;
    const int lid = tid & 31;

    if (tid < EDIM) ksum[tid] = g_ks[tile][tid];
    if (tid < CHK)  dnm[tid] = 0.f;
    __syncthreads();

    const size_t base = (((size_t)n * LSEQ + (size_t)c * CHK) * HEADS + h) * EDIM;

    // ---- stage Q,K (featmap, hi/lo, swizzled) + V; fuse q.ksum partials ----
    {
        const int c4 = (tid & 15) << 2;
        #pragma unroll
        for (int i = 0; i < 8; i++) {
            const int p   = tid + i * 256;
            const int row = p >> 4;
            const size_t g = base + (size_t)row * ROWSTR + c4;
            const float4 qv = *(const float4*)(Qg + g);
            const float4 kv = *(const float4*)(Kg + g);
            const float4 vv = *(const float4*)(Vg + g);
            const float qf[4] = {featmap(qv.x), featmap(qv.y), featmap(qv.z), featmap(qv.w)};
            float part = qf[0] * ksum[c4] + qf[1] * ksum[c4 + 1]
                       + qf[2] * ksum[c4 + 2] + qf[3] * ksum[c4 + 3];
            atomicAdd(&dnm[row], part);

            const uint32_t x = sw((uint32_t)(row * 128 + c4 * 2));
            uint32_t h01, l01, h23, l23;
            split_pack(qf[0], qf[1], h01, l01);
            split_pack(qf[2], qf[3], h23, l23);
            *(uint2*)(smc + QH_OFF + x) = make_uint2(h01, h23);
            *(uint2*)(smc + QL_OFF + x) = make_uint2(l01, l23);
            split_pack(featmap(kv.x), featmap(kv.y), h01, l01);
            split_pack(featmap(kv.z), featmap(kv.w), h23, l23);
            *(uint2*)(smc + KH_OFF + x) = make_uint2(h01, h23);
            *(uint2*)(smc + KL_OFF + x) = make_uint2(l01, l23);
            split_pack(vv.x, vv.y, h01, l01);
            split_pack(vv.z, vv.w, h23, l23);
            *(uint2*)(smc + VH_OFF + x) = make_uint2(h01, h23);
            *(uint2*)(smc + VL_OFF + x) = make_uint2(l01, l23);
        }
    }
    // ---- stage S (hi/lo, swizzled) ----
    {
        const float* Sg = g_S[tile];
        #pragma unroll
        for (int i = 0; i < 8; i++) {
            const int idx = (tid + i * 256) * 2;
            const int e = idx >> 6;
            const int d = idx & 63;
            const float2 s2 = *(const float2*)(Sg + idx);
            __nv_bfloat16 h0, l0, h1, l1;
            split1(s2.x, h0, l0);
            split1(s2.y, h1, l1);
            const uint32_t x = sw((uint32_t)(e * 128 + d * 2));
            *(uint32_t*)(smc + SH_OFF + x) =
                ((uint32_t)__bfloat16_as_ushort(h1) << 16) | __bfloat16_as_ushort(h0);
            *(uint32_t*)(smc + SL_OFF + x) =
                ((uint32_t)__bfloat16_as_ushort(l1) << 16) | __bfloat16_as_ushort(l0);
        }
    }
    __syncthreads();

    const int m0  = wid * 16;
    const int gi  = lid & 7;
    const int grp = lid >> 3;
    const int g1  = grp & 1;
    const int q2  = grp >> 1;
    const int r0  = m0 + (lid >> 2);
    const int r1  = r0 + 8;

    float C2[8][4] = {};
    float rs0 = 0.f, rs1 = 0.f;

    // ---- stream scores in two 64-col halves: MMA1 -> mask/split -> MMA2 ----
    #pragma unroll
    for (int half = 0; half < 2; half++) {
        const int n0 = half * 64;
        float C[8][4] = {};
        #pragma unroll
        for (int kk = 0; kk < EDIM; kk += 16) {
            uint32_t ah[4], al[4];
            const uint32_t ax = sw((uint32_t)((m0 + g1 * 8 + gi) * 128 + (kk + q2 * 8) * 2));
            ldsm_x4(ah, smb + QH_OFF + ax);
            ldsm_x4(al, smb + QL_OFF + ax);
            #pragma unroll
            for (int nt = 0; nt < 8; nt += 2) {
                const uint32_t bx =
                    sw((uint32_t)((n0 + (nt + q2) * 8 + gi) * 128 + (kk + g1 * 8) * 2));
                uint32_t bh[4], bl[4];
                ldsm_x4(bh, smb + KH_OFF + bx);
                ldsm_x4(bl, smb + KL_OFF + bx);
                mma16816(C[nt], ah, bh);
                mma16816(C[nt], ah, bl);
                mma16816(C[nt], al, bh);
                mma16816(C[nt+1], ah, bh + 2);
                mma16816(C[nt+1], ah, bl + 2);
                mma16816(C[nt+1], al, bh + 2);
            }
        }
        // mask + rowsum + split -> feed MMA2 over k = n0..n0+63
        #pragma unroll
        for (int j = 0; j < 4; j++) {
            const int cA = n0 + j * 16 + (lid & 3) * 2;
            const int cB = cA + 8;
            float s00 = (cA     <= r0) ? C[2*j][0]   : 0.f;
            float s01 = (cA + 1 <= r0) ? C[2*j][1]   : 0.f;
            float s02 = (cA     <= r1) ? C[2*j][2]   : 0.f;
            float s03 = (cA + 1 <= r1) ? C[2*j][3]   : 0.f;
            float s10 = (cB     <= r0) ? C[2*j+1][0] : 0.f;
            float s11 = (cB + 1 <= r0) ? C[2*j+1][1] : 0.f;
            float s12 = (cB     <= r1) ? C[2*j+1][2] : 0.f;
            float s13 = (cB + 1 <= r1) ? C[2*j+1][3] : 0.f;
            rs0 += s00 + s01 + s10 + s11;
            rs1 += s02 + s03 + s12 + s13;
            uint32_t ah[4], al[4];
            split_pack(s00, s01, ah[0], al[0]);
            split_pack(s02, s03, ah[1], al[1]);
            split_pack(s10, s11, ah[2], al[2]);
            split_pack(s12, s13, ah[3], al[3]);
            const int brow = n0 + j * 16 + g1 * 8 + gi;
            #pragma unroll
            for (int nt = 0; nt < 8; nt += 2) {
                const uint32_t bx = sw((uint32_t)(brow * 128 + (nt + q2) * 16));
                uint32_t bh[4], bl[4];
                ldsm_x4t(bh, smb + VH_OFF + bx);
                ldsm_x4t(bl, smb + VL_OFF + bx);
                mma16816(C2[nt], ah, bh);
                mma16816(C2[nt], ah, bl);
                mma16816(C2[nt], al, bh);
                mma16816(C2[nt+1], ah, bh + 2);
                mma16816(C2[nt+1], ah, bl + 2);
                mma16816(C2[nt+1], al, bh + 2);
            }
        }
    }
    rs0 += __shfl_xor_sync(0xffffffffu, rs0, 1);
    rs0 += __shfl_xor_sync(0xffffffffu, rs0, 2);
    rs1 += __shfl_xor_sync(0xffffffffu, rs1, 1);
    rs1 += __shfl_xor_sync(0xffffffffu, rs1, 2);
    if ((lid & 3) == 0) {
        atomicAdd(&dnm[r0], rs0);
        atomicAdd(&dnm[r1], rs1);
    }

    // ---- MMA3: C2 += Qf @ S ----
    #pragma unroll
    for (int kk = 0; kk < EDIM; kk += 16) {
        uint32_t ah[4], al[4];
        const uint32_t ax = sw((uint32_t)((m0 + g1 * 8 + gi) * 128 + (kk + q2 * 8) * 2));
        ldsm_x4(ah, smb + QH_OFF + ax);
        ldsm_x4(al, smb + QL_OFF + ax);
        const int brow = kk + g1 * 8 + gi;
        #pragma unroll
        for (int nt = 0; nt < 8; nt += 2) {
            const uint32_t bx = sw((uint32_t)(brow * 128 + (nt + q2) * 16));
            uint32_t bh[4], bl[4];
            ldsm_x4t(bh, smb + SH_OFF + bx);
            ldsm_x4t(bl, smb + SL_OFF + bx);
            mma16816(C2[nt], ah, bh);
            mma16816(C2[nt], ah, bl);
            mma16816(C2[nt], al, bh);
            mma16816(C2[nt+1], ah, bh + 2);
            mma16816(C2[nt+1], ah, bl + 2);
            mma16816(C2[nt+1], al, bh + 2);
        }
    }
    __syncthreads();
    if (tid < CHK) dnm[tid] = 1.f / (dnm[tid] + 1e-6f);
    __syncthreads();

    // ---- epilogue: scale, stage over dead Q/K planes, coalesced STG ----
    {
        const float z0 = dnm[r0];
        const float z1 = dnm[r1];
        #pragma unroll
        for (int nt = 0; nt < 8; nt++) {
            const int cb = nt * 8 + (lid & 3) * 2;
            outb[r0 * 68 + cb]     = C2[nt][0] * z0;
            outb[r0 * 68 + cb + 1] = C2[nt][1] * z0;
            outb[r1 * 68 + cb]     = C2[nt][2] * z1;
            outb[r1 * 68 + cb + 1] = C2[nt][3] * z1;
        }
    }
    __syncthreads();

    const size_t obase = (((size_t)n * LSEQ + (size_t)c * CHK) * HEADS + h) * DDIM;
    {
        const int c4 = (tid & 15) << 2;
        #pragma unroll
        for (int i = 0; i < 8; i++) {
            const int p   = tid + i * 256;
            const int row = p >> 4;
            const float4 v4 = *(const float4*)(outb + row * 68 + c4);
            *(float4*)(out + obase + (size_t)row * ROWSTR + c4) = v4;
        }
    }
}

// ---------------------------------------------------------------------------
extern "C" void kernel_launch(void* const* d_in, const int* in_sizes, int n_in,
                              void* d_out, int out_size) {
    const float* Q = (const float*)d_in[0];
    const float* K = (const float*)d_in[1];
    const float* V = (const float*)d_in[2];
    float* out = (float*)d_out;

    cudaFuncSetAttribute(k_pass1, cudaFuncAttributeMaxDynamicSharedMemorySize, P1_SMEM);
    cudaFuncSetAttribute(k_pass3, cudaFuncAttributeMaxDynamicSharedMemorySize, P3_SMEM);

    k_pass1<<<NTILE, 256, P1_SMEM>>>(K, V);
    k_pass2<<<dim3(4, 64), 256>>>();
    k_pass3<<<NTILE, 256, P3_SMEM>>>(Q, K, V, out);
}

// round 6
// speedup vs baseline: 4.1708x; 1.1499x over previous
#include <cuda_runtime.h>
#include <cuda_bf16.h>
#include <cstdint>

// Problem constants (fixed shapes)
#define NBATCH 4
#define LSEQ   8192
#define HEADS  16
#define EDIM   64
#define DDIM   64
#define CHK    128
#define NCH    64
#define NTILE  (NBATCH*HEADS*NCH)      // 4096
#define ROWSTR (HEADS*EDIM)            // 1024

__device__ float g_S [NTILE][EDIM*DDIM];   // 64 MB
__device__ float g_ks[NTILE][EDIM];        // 1 MB

__device__ __forceinline__ float featmap(float x) {
    return x > 0.f ? x + 1.f : __expf(x);
}
__device__ __forceinline__ uint32_t smem_u32(const void* p) {
    return (uint32_t)__cvta_generic_to_shared(p);
}
__device__ __forceinline__ uint32_t sw(uint32_t x) { return x ^ ((x >> 3) & 0x70); }

// ---- warp-level tensor core primitives --------------------------------------
__device__ __forceinline__ void mma16816(float* c, const uint32_t* a, const uint32_t* b) {
    asm volatile(
        "mma.sync.aligned.m16n8k16.row.col.f32.bf16.bf16.f32 "
        "{%0,%1,%2,%3}, {%4,%5,%6,%7}, {%8,%9}, {%0,%1,%2,%3};"
        : "+f"(c[0]), "+f"(c[1]), "+f"(c[2]), "+f"(c[3])
        : "r"(a[0]), "r"(a[1]), "r"(a[2]), "r"(a[3]), "r"(b[0]), "r"(b[1]));
}
__device__ __forceinline__ void ldsm_x4(uint32_t* r, uint32_t addr) {
    asm volatile("ldmatrix.sync.aligned.m8n8.x4.shared.b16 {%0,%1,%2,%3}, [%4];"
                 : "=r"(r[0]), "=r"(r[1]), "=r"(r[2]), "=r"(r[3]) : "r"(addr));
}
__device__ __forceinline__ void ldsm_x4t(uint32_t* r, uint32_t addr) {
    asm volatile("ldmatrix.sync.aligned.m8n8.x4.trans.shared.b16 {%0,%1,%2,%3}, [%4];"
                 : "=r"(r[0]), "=r"(r[1]), "=r"(r[2]), "=r"(r[3]) : "r"(addr));
}

__device__ __forceinline__ void split_pack(float a, float b, uint32_t& hi, uint32_t& lo) {
    __nv_bfloat16 ah = __float2bfloat16(a), bh = __float2bfloat16(b);
    __nv_bfloat16 al = __float2bfloat16(a - __bfloat162float(ah));
    __nv_bfloat16 bl = __float2bfloat16(b - __bfloat162float(bh));
    hi = ((uint32_t)__bfloat16_as_ushort(bh) << 16) | (uint32_t)__bfloat16_as_ushort(ah);
    lo = ((uint32_t)__bfloat16_as_ushort(bl) << 16) | (uint32_t)__bfloat16_as_ushort(al);
}
__device__ __forceinline__ void split1(float a, __nv_bfloat16& hi, __nv_bfloat16& lo) {
    hi = __float2bfloat16(a);
    lo = __float2bfloat16(a - __bfloat162float(hi));
}

// ---------------------------------------------------------------------------
// Pass 1: S_c = phi(K)^T V  (64x64, k=128) ; ksum_c.   block=256, grid=4096
// ---------------------------------------------------------------------------
#define P1_KH 0
#define P1_KL 16384
#define P1_VH 32768
#define P1_VL 49152
#define P1_KS 65536
#define P1_SMEM (P1_KS + 256)

__global__ void __launch_bounds__(256) k_pass1(const float* __restrict__ keys,
                                               const float* __restrict__ values) {
    extern __shared__ char smc[];
    const uint32_t smb = smem_u32(smc);
    float* ksum = (float*)(smc + P1_KS);

    const int tile = blockIdx.x;
    const int c  = tile & (NCH - 1);
    const int nh = tile >> 6;
    const int h  = nh & (HEADS - 1);
    const int n  = nh >> 4;
    const int tid = threadIdx.x;
    const int wid = tid >> 5;
    const int lid = tid & 31;

    if (tid < EDIM) ksum[tid] = 0.f;
    __syncthreads();

    const size_t base = (((size_t)n * LSEQ + (size_t)c * CHK) * HEADS + h) * EDIM;

    float ksr[4] = {0.f, 0.f, 0.f, 0.f};
    const int c4 = (tid & 15) << 2;
    #pragma unroll
    for (int i = 0; i < 8; i++) {
        const int p   = tid + i * 256;
        const int row = p >> 4;
        const size_t g = base + (size_t)row * ROWSTR + c4;
        const float4 kv = *(const float4*)(keys   + g);
        const float4 vv = *(const float4*)(values + g);
        const float kf[4] = {featmap(kv.x), featmap(kv.y), featmap(kv.z), featmap(kv.w)};
        #pragma unroll
        for (int j = 0; j < 4; j++) ksr[j] += kf[j];

        const uint32_t x = sw((uint32_t)(row * 128 + c4 * 2));
        uint32_t h01, l01, h23, l23;
        split_pack(kf[0], kf[1], h01, l01);
        split_pack(kf[2], kf[3], h23, l23);
        *(uint2*)(smc + P1_KH + x) = make_uint2(h01, h23);
        *(uint2*)(smc + P1_KL + x) = make_uint2(l01, l23);
        split_pack(vv.x, vv.y, h01, l01);
        split_pack(vv.z, vv.w, h23, l23);
        *(uint2*)(smc + P1_VH + x) = make_uint2(h01, h23);
        *(uint2*)(smc + P1_VL + x) = make_uint2(l01, l23);
    }
    #pragma unroll
    for (int j = 0; j < 4; j++) atomicAdd(&ksum[c4 + j], ksr[j]);
    __syncthreads();

    if (tid < EDIM) g_ks[tile][tid] = ksum[tid];

    const int mrow  = (wid & 3) * 16;
    const int nhalf = (wid >> 2) * 32;
    const int gi  = lid & 7;
    const int grp = lid >> 3;
    const int g1  = grp & 1;
    const int q2  = grp >> 1;
    float C[4][4] = {};
    for (int kk = 0; kk < CHK; kk += 16) {
        uint32_t ah[4], al[4];
        const int arow = kk + ((grp & 2) ? 8 : 0) + gi;
        const int acol = mrow + ((grp & 1) ? 8 : 0);
        const uint32_t ax = sw((uint32_t)(arow * 128 + acol * 2));
        ldsm_x4t(ah, smb + P1_KH + ax);
        ldsm_x4t(al, smb + P1_KL + ax);
        const int brow = kk + g1 * 8 + gi;
        #pragma unroll
        for (int nt = 0; nt < 4; nt += 2) {
            const uint32_t bx = sw((uint32_t)(brow * 128 + (nhalf + (nt + q2) * 8) * 2));
            uint32_t bh[4], bl[4];
            ldsm_x4t(bh, smb + P1_VH + bx);
            ldsm_x4t(bl, smb + P1_VL + bx);
            mma16816(C[nt], ah, bh);
            mma16816(C[nt], ah, bl);
            mma16816(C[nt], al, bh);
            mma16816(C[nt+1], ah, bh + 2);
            mma16816(C[nt+1], ah, bl + 2);
            mma16816(C[nt+1], al, bh + 2);
        }
    }
    float* So = g_S[tile];
    const int e0 = mrow + (lid >> 2);
    const int e1 = e0 + 8;
    #pragma unroll
    for (int nt = 0; nt < 4; nt++) {
        const int d = nhalf + nt * 8 + (lid & 3) * 2;
        *(float2*)(So + e0 * 64 + d) = make_float2(C[nt][0], C[nt][1]);
        *(float2*)(So + e1 * 64 + d) = make_float2(C[nt][2], C[nt][3]);
    }
}

// ---------------------------------------------------------------------------
// Pass 2: exclusive prefix over chunks, float4 per thread. grid=(4,64)
// ---------------------------------------------------------------------------
__global__ void __launch_bounds__(256) k_pass2() {
    const int nh  = blockIdx.y;
    const int idx = (blockIdx.x * 256 + threadIdx.x) * 4;
    const int base = nh * NCH;

    float4 run = make_float4(0.f, 0.f, 0.f, 0.f);
    #pragma unroll 4
    for (int c = 0; c < NCH; c++) {
        float4* p = (float4*)&g_S[base + c][idx];
        const float4 t = *p;
        *p = run;
        run.x += t.x; run.y += t.y; run.z += t.z; run.w += t.w;
    }
    if (blockIdx.x == 0 && threadIdx.x < EDIM) {
        const int e = threadIdx.x;
        float kr = 0.f;
        #pragma unroll 4
        for (int c = 0; c < NCH; c++) {
            const float t = g_ks[base + c][e];
            g_ks[base + c][e] = kr;
            kr += t;
        }
    }
}

// ---------------------------------------------------------------------------
// Pass 3: out = (Qf@S + tril(Qf Kf^T)@V) / (Qf.ksum + rowsum)
// Triangular scheduling: warp with row-block rb computes only col-groups <= rb.
// rb = wid<4 ? wid : 11-wid  -> SMSP pairs sum to constant work.
// ---------------------------------------------------------------------------
#define QH_OFF   0
#define QL_OFF   16384
#define KH_OFF   32768
#define KL_OFF   49152
#define VH_OFF   65536
#define VL_OFF   81920
#define SH_OFF   98304
#define SL_OFF   106496
#define KSUM_OFF 114688
#define DNM_OFF  114944
#define P3_SMEM  115456
#define OUTB_OFF 0          // reuse Q/K planes for f32 [128][68] staging

__global__ void __launch_bounds__(256, 2) k_pass3(const float* __restrict__ Qg,
                                                  const float* __restrict__ Kg,
                                                  const float* __restrict__ Vg,
                                                  float* __restrict__ out) {
    extern __shared__ char smc[];
    const uint32_t smb = smem_u32(smc);
    float* ksum = (float*)(smc + KSUM_OFF);
    float* dnm  = (float*)(smc + DNM_OFF);
    float* outb = (float*)(smc + OUTB_OFF);

    const int tile = blockIdx.x;
    const int c  = tile & (NCH - 1);
    const int nh = tile >> 6;
    const int h  = nh & (HEADS - 1);
    const int n  = nh >> 4;
    const int tid = threadIdx.x;
    const int wid = tid >> 5;
    const int lid = tid & 31;

    if (tid < EDIM) ksum[tid] = g_ks[tile][tid];
    if (tid < CHK)  dnm[tid] = 0.f;
    __syncthreads();

    const size_t base = (((size_t)n * LSEQ + (size_t)c * CHK) * HEADS + h) * EDIM;

    // ---- stage Q,K (featmap, hi/lo, swizzled) + V; fuse q.ksum partials ----
    {
        const int c4 = (tid & 15) << 2;
        #pragma unroll
        for (int i = 0; i < 8; i++) {
            const int p   = tid + i * 256;
            const int row = p >> 4;
            const size_t g = base + (size_t)row * ROWSTR + c4;
            const float4 qv = *(const float4*)(Qg + g);
            const float4 kv = *(const float4*)(Kg + g);
            const float4 vv = *(const float4*)(Vg + g);
            const float qf[4] = {featmap(qv.x), featmap(qv.y), featmap(qv.z), featmap(qv.w)};
            float part = qf[0] * ksum[c4] + qf[1] * ksum[c4 + 1]
                       + qf[2] * ksum[c4 + 2] + qf[3] * ksum[c4 + 3];
            // lanes 0..15 share one row, lanes 16..31 the next: 16-lane reduce
            part += __shfl_xor_sync(0xffffffffu, part, 1);
            part += __shfl_xor_sync(0xffffffffu, part, 2);
            part += __shfl_xor_sync(0xffffffffu, part, 4);
            part += __shfl_xor_sync(0xffffffffu, part, 8);
            if ((lid & 15) == 0) atomicAdd(&dnm[row], part);

            const uint32_t x = sw((uint32_t)(row * 128 + c4 * 2));
            uint32_t h01, l01, h23, l23;
            split_pack(qf[0], qf[1], h01, l01);
            split_pack(qf[2], qf[3], h23, l23);
            *(uint2*)(smc + QH_OFF + x) = make_uint2(h01, h23);
            *(uint2*)(smc + QL_OFF + x) = make_uint2(l01, l23);
            split_pack(featmap(kv.x), featmap(kv.y), h01, l01);
            split_pack(featmap(kv.z), featmap(kv.w), h23, l23);
            *(uint2*)(smc + KH_OFF + x) = make_uint2(h01, h23);
            *(uint2*)(smc + KL_OFF + x) = make_uint2(l01, l23);
            split_pack(vv.x, vv.y, h01, l01);
            split_pack(vv.z, vv.w, h23, l23);
            *(uint2*)(smc + VH_OFF + x) = make_uint2(h01, h23);
            *(uint2*)(smc + VL_OFF + x) = make_uint2(l01, l23);
        }
    }
    // ---- stage S (hi/lo, swizzled) ----
    {
        const float* Sg = g_S[tile];
        #pragma unroll
        for (int i = 0; i < 8; i++) {
            const int idx = (tid + i * 256) * 2;
            const int e = idx >> 6;
            const int d = idx & 63;
            const float2 s2 = *(const float2*)(Sg + idx);
            __nv_bfloat16 h0, l0, h1, l1;
            split1(s2.x, h0, l0);
            split1(s2.y, h1, l1);
            const uint32_t x = sw((uint32_t)(e * 128 + d * 2));
            *(uint32_t*)(smc + SH_OFF + x) =
                ((uint32_t)__bfloat16_as_ushort(h1) << 16) | __bfloat16_as_ushort(h0);
            *(uint32_t*)(smc + SL_OFF + x) =
                ((uint32_t)__bfloat16_as_ushort(l1) << 16) | __bfloat16_as_ushort(l0);
        }
    }
    __syncthreads();

    // row-block assignment: SMSP pairs (w, w+4) get rb sums of 7 (balanced)
    const int rb  = (wid < 4) ? wid : 11 - wid;
    const int m0  = rb * 16;
    const int gi  = lid & 7;
    const int grp = lid >> 3;
    const int g1  = grp & 1;
    const int q2  = grp >> 1;
    const int r0  = m0 + (lid >> 2);
    const int r1  = r0 + 8;

    // hoist Q fragments (reused by MMA1 per jg and MMA3)
    uint32_t aqh[4][4], aql[4][4];
    #pragma unroll
    for (int t = 0; t < 4; t++) {
        const uint32_t ax = sw((uint32_t)((m0 + g1 * 8 + gi) * 128 + (t * 16 + q2 * 8) * 2));
        ldsm_x4(aqh[t], smb + QH_OFF + ax);
        ldsm_x4(aql[t], smb + QL_OFF + ax);
    }

    float C2[8][4] = {};
    float rs0 = 0.f, rs1 = 0.f;

    // ---- triangular: for each 16-col group jg <= rb: MMA1 -> split -> MMA2 ----
    for (int jg = 0; jg <= rb; jg++) {
        float Ct[2][4] = {};
        #pragma unroll
        for (int t = 0; t < 4; t++) {
            const uint32_t bx =
                sw((uint32_t)((jg * 16 + q2 * 8 + gi) * 128 + (t * 16 + g1 * 8) * 2));
            uint32_t bh[4], bl[4];
            ldsm_x4(bh, smb + KH_OFF + bx);
            ldsm_x4(bl, smb + KL_OFF + bx);
            mma16816(Ct[0], aqh[t], bh);
            mma16816(Ct[0], aqh[t], bl);
            mma16816(Ct[0], aql[t], bh);
            mma16816(Ct[1], aqh[t], bh + 2);
            mma16816(Ct[1], aqh[t], bl + 2);
            mma16816(Ct[1], aql[t], bh + 2);
        }
        float s00 = Ct[0][0], s01 = Ct[0][1], s02 = Ct[0][2], s03 = Ct[0][3];
        float s10 = Ct[1][0], s11 = Ct[1][1], s12 = Ct[1][2], s13 = Ct[1][3];
        if (jg == rb) {   // diagonal block: apply causal mask
            const int cA = jg * 16 + (lid & 3) * 2;
            const int cB = cA + 8;
            s00 = (cA     <= r0) ? s00 : 0.f;
            s01 = (cA + 1 <= r0) ? s01 : 0.f;
            s02 = (cA     <= r1) ? s02 : 0.f;
            s03 = (cA + 1 <= r1) ? s03 : 0.f;
            s10 = (cB     <= r0) ? s10 : 0.f;
            s11 = (cB + 1 <= r0) ? s11 : 0.f;
            s12 = (cB     <= r1) ? s12 : 0.f;
            s13 = (cB + 1 <= r1) ? s13 : 0.f;
        }
        rs0 += s00 + s01 + s10 + s11;
        rs1 += s02 + s03 + s12 + s13;
        uint32_t a2h[4], a2l[4];
        split_pack(s00, s01, a2h[0], a2l[0]);
        split_pack(s02, s03, a2h[1], a2l[1]);
        split_pack(s10, s11, a2h[2], a2l[2]);
        split_pack(s12, s13, a2h[3], a2l[3]);
        const int brow = jg * 16 + g1 * 8 + gi;
        #pragma unroll
        for (int nt = 0; nt < 8; nt += 2) {
            const uint32_t bx = sw((uint32_t)(brow * 128 + (nt + q2) * 16));
            uint32_t bh[4], bl[4];
            ldsm_x4t(bh, smb + VH_OFF + bx);
            ldsm_x4t(bl, smb + VL_OFF + bx);
            mma16816(C2[nt], a2h, bh);
            mma16816(C2[nt], a2h, bl);
            mma16816(C2[nt], a2l, bh);
            mma16816(C2[nt+1], a2h, bh + 2);
            mma16816(C2[nt+1], a2h, bl + 2);
            mma16816(C2[nt+1], a2l, bh + 2);
        }
    }
    rs0 += __shfl_xor_sync(0xffffffffu, rs0, 1);
    rs0 += __shfl_xor_sync(0xffffffffu, rs0, 2);
    rs1 += __shfl_xor_sync(0xffffffffu, rs1, 1);
    rs1 += __shfl_xor_sync(0xffffffffu, rs1, 2);
    if ((lid & 3) == 0) {
        atomicAdd(&dnm[r0], rs0);
        atomicAdd(&dnm[r1], rs1);
    }

    // ---- MMA3: C2 += Qf @ S (reuses hoisted Q fragments) ----
    #pragma unroll
    for (int t = 0; t < 4; t++) {
        const int brow = t * 16 + g1 * 8 + gi;
        #pragma unroll
        for (int nt = 0; nt < 8; nt += 2) {
            const uint32_t bx = sw((uint32_t)(brow * 128 + (nt + q2) * 16));
            uint32_t bh[4], bl[4];
            ldsm_x4t(bh, smb + SH_OFF + bx);
            ldsm_x4t(bl, smb + SL_OFF + bx);
            mma16816(C2[nt], aqh[t], bh);
            mma16816(C2[nt], aqh[t], bl);
            mma16816(C2[nt], aql[t], bh);
            mma16816(C2[nt+1], aqh[t], bh + 2);
            mma16816(C2[nt+1], aqh[t], bl + 2);
            mma16816(C2[nt+1], aql[t], bh + 2);
        }
    }
    __syncthreads();
    if (tid < CHK) dnm[tid] = 1.f / (dnm[tid] + 1e-6f);
    __syncthreads();

    // ---- epilogue: scale, stage over dead Q/K planes, coalesced STG ----
    {
        const float z0 = dnm[r0];
        const float z1 = dnm[r1];
        #pragma unroll
        for (int nt = 0; nt < 8; nt++) {
            const int cb = nt * 8 + (lid & 3) * 2;
            outb[r0 * 68 + cb]     = C2[nt][0] * z0;
            outb[r0 * 68 + cb + 1] = C2[nt][1] * z0;
            outb[r1 * 68 + cb]     = C2[nt][2] * z1;
            outb[r1 * 68 + cb + 1] = C2[nt][3] * z1;
        }
    }
    __syncthreads();

    const size_t obase = (((size_t)n * LSEQ + (size_t)c * CHK) * HEADS + h) * DDIM;
    {
        const int c4 = (tid & 15) << 2;
        #pragma unroll
        for (int i = 0; i < 8; i++) {
            const int p   = tid + i * 256;
            const int row = p >> 4;
            const float4 v4 = *(const float4*)(outb + row * 68 + c4);
            *(float4*)(out + obase + (size_t)row * ROWSTR + c4) = v4;
        }
    }
}

// ---------------------------------------------------------------------------
extern "C" void kernel_launch(void* const* d_in, const int* in_sizes, int n_in,
                              void* d_out, int out_size) {
    const float* Q = (const float*)d_in[0];
    const float* K = (const float*)d_in[1];
    const float* V = (const float*)d_in[2];
    float* out = (float*)d_out;

    cudaFuncSetAttribute(k_pass1, cudaFuncAttributeMaxDynamicSharedMemorySize, P1_SMEM);
    cudaFuncSetAttribute(k_pass3, cudaFuncAttributeMaxDynamicSharedMemorySize, P3_SMEM);

    k_pass1<<<NTILE, 256, P1_SMEM>>>(K, V);
    k_pass2<<<dim3(4, 64), 256>>>();
    k_pass3<<<NTILE, 256, P3_SMEM>>>(Q, K, V, out);
}

// round 7
// speedup vs baseline: 4.5054x; 1.0802x over previous
#include <cuda_runtime.h>
#include <cuda_bf16.h>
#include <cstdint>

// Problem constants (fixed shapes)
#define NBATCH 4
#define LSEQ   8192
#define HEADS  16
#define EDIM   64
#define DDIM   64
#define CHK    128
#define NCH    64
#define NTILE  (NBATCH*HEADS*NCH)      // 4096
#define ROWSTR (HEADS*EDIM)            // 1024

__device__ float g_S [NTILE][EDIM*DDIM];   // 64 MB
__device__ float g_ks[NTILE][EDIM];        // 1 MB

__device__ __forceinline__ float featmap(float x) {
    return x > 0.f ? x + 1.f : __expf(x);
}
__device__ __forceinline__ uint32_t smem_u32(const void* p) {
    return (uint32_t)__cvta_generic_to_shared(p);
}
__device__ __forceinline__ uint32_t sw(uint32_t x) { return x ^ ((x >> 3) & 0x70); }

// ---- warp-level tensor core primitives --------------------------------------
__device__ __forceinline__ void mma16816(float* c, const uint32_t* a, const uint32_t* b) {
    asm volatile(
        "mma.sync.aligned.m16n8k16.row.col.f32.bf16.bf16.f32 "
        "{%0,%1,%2,%3}, {%4,%5,%6,%7}, {%8,%9}, {%0,%1,%2,%3};"
        : "+f"(c[0]), "+f"(c[1]), "+f"(c[2]), "+f"(c[3])
        : "r"(a[0]), "r"(a[1]), "r"(a[2]), "r"(a[3]), "r"(b[0]), "r"(b[1]));
}
__device__ __forceinline__ void ldsm_x4(uint32_t* r, uint32_t addr) {
    asm volatile("ldmatrix.sync.aligned.m8n8.x4.shared.b16 {%0,%1,%2,%3}, [%4];"
                 : "=r"(r[0]), "=r"(r[1]), "=r"(r[2]), "=r"(r[3]) : "r"(addr));
}
__device__ __forceinline__ void ldsm_x4t(uint32_t* r, uint32_t addr) {
    asm volatile("ldmatrix.sync.aligned.m8n8.x4.trans.shared.b16 {%0,%1,%2,%3}, [%4];"
                 : "=r"(r[0]), "=r"(r[1]), "=r"(r[2]), "=r"(r[3]) : "r"(addr));
}

// fast hi/lo split: hi = truncated-bf16 pair (one PRMT), lo = exact residual
// packed with one cvt.rn.bf16x2.f32. Residual a - trunc(a) is exact in fp32.
__device__ __forceinline__ uint32_t pack_bf16x2(float lo, float hi) {
    uint32_t r;
    asm("cvt.rn.bf16x2.f32 %0, %1, %2;" : "=r"(r) : "f"(hi), "f"(lo));
    return r;
}
__device__ __forceinline__ void split_pack(float a, float b, uint32_t& hi, uint32_t& lo) {
    const uint32_t au = __float_as_uint(a), bu = __float_as_uint(b);
    hi = __byte_perm(au, bu, 0x7632);
    const float la = a - __uint_as_float(au & 0xFFFF0000u);
    const float lb = b - __uint_as_float(bu & 0xFFFF0000u);
    lo = pack_bf16x2(la, lb);
}

// ---------------------------------------------------------------------------
// Pass 1: S_c = phi(K)^T V  (64x64, k=128) ; ksum_c.   block=256, grid=4096
// ---------------------------------------------------------------------------
#define P1_KH 0
#define P1_KL 16384
#define P1_VH 32768
#define P1_VL 49152
#define P1_KS 65536
#define P1_SMEM (P1_KS + 256)

__global__ void __launch_bounds__(256) k_pass1(const float* __restrict__ keys,
                                               const float* __restrict__ values) {
    extern __shared__ char smc[];
    const uint32_t smb = smem_u32(smc);
    float* ksum = (float*)(smc + P1_KS);

    const int tile = blockIdx.x;
    const int c  = tile & (NCH - 1);
    const int nh = tile >> 6;
    const int h  = nh & (HEADS - 1);
    const int n  = nh >> 4;
    const int tid = threadIdx.x;
    const int wid = tid >> 5;
    const int lid = tid & 31;

    if (tid < EDIM) ksum[tid] = 0.f;
    __syncthreads();

    const size_t base = (((size_t)n * LSEQ + (size_t)c * CHK) * HEADS + h) * EDIM;

    float ksr[4] = {0.f, 0.f, 0.f, 0.f};
    const int c4 = (tid & 15) << 2;
    #pragma unroll
    for (int i = 0; i < 8; i++) {
        const int p   = tid + i * 256;
        const int row = p >> 4;
        const size_t g = base + (size_t)row * ROWSTR + c4;
        const float4 kv = *(const float4*)(keys   + g);
        const float4 vv = *(const float4*)(values + g);
        const float kf[4] = {featmap(kv.x), featmap(kv.y), featmap(kv.z), featmap(kv.w)};
        #pragma unroll
        for (int j = 0; j < 4; j++) ksr[j] += kf[j];

        const uint32_t x = sw((uint32_t)(row * 128 + c4 * 2));
        uint32_t h01, l01, h23, l23;
        split_pack(kf[0], kf[1], h01, l01);
        split_pack(kf[2], kf[3], h23, l23);
        *(uint2*)(smc + P1_KH + x) = make_uint2(h01, h23);
        *(uint2*)(smc + P1_KL + x) = make_uint2(l01, l23);
        split_pack(vv.x, vv.y, h01, l01);
        split_pack(vv.z, vv.w, h23, l23);
        *(uint2*)(smc + P1_VH + x) = make_uint2(h01, h23);
        *(uint2*)(smc + P1_VL + x) = make_uint2(l01, l23);
    }
    // lanes lid and lid+16 share c4 -> shfl-combine, then half the atomics
    #pragma unroll
    for (int j = 0; j < 4; j++) {
        ksr[j] += __shfl_xor_sync(0xffffffffu, ksr[j], 16);
        if (lid < 16) atomicAdd(&ksum[c4 + j], ksr[j]);
    }
    __syncthreads();

    if (tid < EDIM) g_ks[tile][tid] = ksum[tid];

    const int mrow  = (wid & 3) * 16;
    const int nhalf = (wid >> 2) * 32;
    const int gi  = lid & 7;
    const int grp = lid >> 3;
    const int g1  = grp & 1;
    const int q2  = grp >> 1;
    float C[4][4] = {};
    for (int kk = 0; kk < CHK; kk += 16) {
        uint32_t ah[4], al[4];
        const int arow = kk + ((grp & 2) ? 8 : 0) + gi;
        const int acol = mrow + ((grp & 1) ? 8 : 0);
        const uint32_t ax = sw((uint32_t)(arow * 128 + acol * 2));
        ldsm_x4t(ah, smb + P1_KH + ax);
        ldsm_x4t(al, smb + P1_KL + ax);
        const int brow = kk + g1 * 8 + gi;
        #pragma unroll
        for (int nt = 0; nt < 4; nt += 2) {
            const uint32_t bx = sw((uint32_t)(brow * 128 + (nhalf + (nt + q2) * 8) * 2));
            uint32_t bh[4], bl[4];
            ldsm_x4t(bh, smb + P1_VH + bx);
            ldsm_x4t(bl, smb + P1_VL + bx);
            mma16816(C[nt], ah, bh);
            mma16816(C[nt], ah, bl);
            mma16816(C[nt], al, bh);
            mma16816(C[nt+1], ah, bh + 2);
            mma16816(C[nt+1], ah, bl + 2);
            mma16816(C[nt+1], al, bh + 2);
        }
    }
    float* So = g_S[tile];
    const int e0 = mrow + (lid >> 2);
    const int e1 = e0 + 8;
    #pragma unroll
    for (int nt = 0; nt < 4; nt++) {
        const int d = nhalf + nt * 8 + (lid & 3) * 2;
        *(float2*)(So + e0 * 64 + d) = make_float2(C[nt][0], C[nt][1]);
        *(float2*)(So + e1 * 64 + d) = make_float2(C[nt][2], C[nt][3]);
    }
}

// ---------------------------------------------------------------------------
// Pass 2: exclusive prefix over chunks, float4 per thread. grid=(4,64)
// ---------------------------------------------------------------------------
__global__ void __launch_bounds__(256) k_pass2() {
    const int nh  = blockIdx.y;
    const int idx = (blockIdx.x * 256 + threadIdx.x) * 4;
    const int base = nh * NCH;

    float4 run = make_float4(0.f, 0.f, 0.f, 0.f);
    #pragma unroll 8
    for (int c = 0; c < NCH; c++) {
        float4* p = (float4*)&g_S[base + c][idx];
        const float4 t = *p;
        *p = run;
        run.x += t.x; run.y += t.y; run.z += t.z; run.w += t.w;
    }
    if (blockIdx.x == 0 && threadIdx.x < EDIM) {
        const int e = threadIdx.x;
        float kr = 0.f;
        #pragma unroll 8
        for (int c = 0; c < NCH; c++) {
            const float t = g_ks[base + c][e];
            g_ks[base + c][e] = kr;
            kr += t;
        }
    }
}

// ---------------------------------------------------------------------------
// Pass 3: out = (Qf@S + tril(Qf Kf^T)@V) / (Qf.ksum + rowsum)
// Triangular warp scheduling; S staged into dead K planes after the jg loop.
// smem ~97KB -> 2 CTAs/SM guaranteed.
// ---------------------------------------------------------------------------
#define QH_OFF   0
#define QL_OFF   16384
#define KH_OFF   32768
#define KL_OFF   49152
#define VH_OFF   65536
#define VL_OFF   81920
#define KSUM_OFF 98304
#define DNM_OFF  98560
#define P3_SMEM  99328
#define OUTB_OFF 0          // f32 [128][68] staging over dead Q planes (+2KB into KH)

__global__ void __launch_bounds__(256, 2) k_pass3(const float* __restrict__ Qg,
                                                  const float* __restrict__ Kg,
                                                  const float* __restrict__ Vg,
                                                  float* __restrict__ out) {
    extern __shared__ char smc[];
    const uint32_t smb = smem_u32(smc);
    float* ksum = (float*)(smc + KSUM_OFF);
    float* dnm  = (float*)(smc + DNM_OFF);
    float* outb = (float*)(smc + OUTB_OFF);

    const int tile = blockIdx.x;
    const int c  = tile & (NCH - 1);
    const int nh = tile >> 6;
    const int h  = nh & (HEADS - 1);
    const int n  = nh >> 4;
    const int tid = threadIdx.x;
    const int wid = tid >> 5;
    const int lid = tid & 31;

    if (tid < EDIM) ksum[tid] = g_ks[tile][tid];
    if (tid < CHK)  dnm[tid] = 0.f;
    __syncthreads();

    const size_t base = (((size_t)n * LSEQ + (size_t)c * CHK) * HEADS + h) * EDIM;

    // ---- stage Q,K (featmap, hi/lo, swizzled) + V; fuse q.ksum partials ----
    {
        const int c4 = (tid & 15) << 2;
        #pragma unroll
        for (int i = 0; i < 8; i++) {
            const int p   = tid + i * 256;
            const int row = p >> 4;
            const size_t g = base + (size_t)row * ROWSTR + c4;
            const float4 qv = *(const float4*)(Qg + g);
            const float4 kv = *(const float4*)(Kg + g);
            const float4 vv = *(const float4*)(Vg + g);
            const float qf[4] = {featmap(qv.x), featmap(qv.y), featmap(qv.z), featmap(qv.w)};
            float part = qf[0] * ksum[c4] + qf[1] * ksum[c4 + 1]
                       + qf[2] * ksum[c4 + 2] + qf[3] * ksum[c4 + 3];
            part += __shfl_xor_sync(0xffffffffu, part, 1);
            part += __shfl_xor_sync(0xffffffffu, part, 2);
            part += __shfl_xor_sync(0xffffffffu, part, 4);
            part += __shfl_xor_sync(0xffffffffu, part, 8);
            if ((lid & 15) == 0) atomicAdd(&dnm[row], part);

            const uint32_t x = sw((uint32_t)(row * 128 + c4 * 2));
            uint32_t h01, l01, h23, l23;
            split_pack(qf[0], qf[1], h01, l01);
            split_pack(qf[2], qf[3], h23, l23);
            *(uint2*)(smc + QH_OFF + x) = make_uint2(h01, h23);
            *(uint2*)(smc + QL_OFF + x) = make_uint2(l01, l23);
            split_pack(featmap(kv.x), featmap(kv.y), h01, l01);
            split_pack(featmap(kv.z), featmap(kv.w), h23, l23);
            *(uint2*)(smc + KH_OFF + x) = make_uint2(h01, h23);
            *(uint2*)(smc + KL_OFF + x) = make_uint2(l01, l23);
            split_pack(vv.x, vv.y, h01, l01);
            split_pack(vv.z, vv.w, h23, l23);
            *(uint2*)(smc + VH_OFF + x) = make_uint2(h01, h23);
            *(uint2*)(smc + VL_OFF + x) = make_uint2(l01, l23);
        }
    }
    __syncthreads();

    // row-block assignment: SMSP pairs (w, w+4) get rb sums of 7 (balanced)
    const int rb  = (wid < 4) ? wid : 11 - wid;
    const int m0  = rb * 16;
    const int gi  = lid & 7;
    const int grp = lid >> 3;
    const int g1  = grp & 1;
    const int q2  = grp >> 1;
    const int r0  = m0 + (lid >> 2);
    const int r1  = r0 + 8;

    // hoist Q fragments (reused by MMA1 per jg and MMA3)
    uint32_t aqh[4][4], aql[4][4];
    #pragma unroll
    for (int t = 0; t < 4; t++) {
        const uint32_t ax = sw((uint32_t)((m0 + g1 * 8 + gi) * 128 + (t * 16 + q2 * 8) * 2));
        ldsm_x4(aqh[t], smb + QH_OFF + ax);
        ldsm_x4(aql[t], smb + QL_OFF + ax);
    }

    float C2[8][4] = {};
    float rs0 = 0.f, rs1 = 0.f;

    // ---- triangular: for each 16-col group jg <= rb: MMA1 -> split -> MMA2 ----
    for (int jg = 0; jg <= rb; jg++) {
        float Ct[2][4] = {};
        #pragma unroll
        for (int t = 0; t < 4; t++) {
            const uint32_t bx =
                sw((uint32_t)((jg * 16 + q2 * 8 + gi) * 128 + (t * 16 + g1 * 8) * 2));
            uint32_t bh[4], bl[4];
            ldsm_x4(bh, smb + KH_OFF + bx);
            ldsm_x4(bl, smb + KL_OFF + bx);
            mma16816(Ct[0], aqh[t], bh);
            mma16816(Ct[0], aqh[t], bl);
            mma16816(Ct[0], aql[t], bh);
            mma16816(Ct[1], aqh[t], bh + 2);
            mma16816(Ct[1], aqh[t], bl + 2);
            mma16816(Ct[1], aql[t], bh + 2);
        }
        float s00 = Ct[0][0], s01 = Ct[0][1], s02 = Ct[0][2], s03 = Ct[0][3];
        float s10 = Ct[1][0], s11 = Ct[1][1], s12 = Ct[1][2], s13 = Ct[1][3];
        if (jg == rb) {   // diagonal block: causal mask
            const int cA = jg * 16 + (lid & 3) * 2;
            const int cB = cA + 8;
            s00 = (cA     <= r0) ? s00 : 0.f;
            s01 = (cA + 1 <= r0) ? s01 : 0.f;
            s02 = (cA     <= r1) ? s02 : 0.f;
            s03 = (cA + 1 <= r1) ? s03 : 0.f;
            s10 = (cB     <= r0) ? s10 : 0.f;
            s11 = (cB + 1 <= r0) ? s11 : 0.f;
            s12 = (cB     <= r1) ? s12 : 0.f;
            s13 = (cB + 1 <= r1) ? s13 : 0.f;
        }
        rs0 += s00 + s01 + s10 + s11;
        rs1 += s02 + s03 + s12 + s13;
        uint32_t a2h[4], a2l[4];
        split_pack(s00, s01, a2h[0], a2l[0]);
        split_pack(s02, s03, a2h[1], a2l[1]);
        split_pack(s10, s11, a2h[2], a2l[2]);
        split_pack(s12, s13, a2h[3], a2l[3]);
        const int brow = jg * 16 + g1 * 8 + gi;
        #pragma unroll
        for (int nt = 0; nt < 8; nt += 2) {
            const uint32_t bx = sw((uint32_t)(brow * 128 + (nt + q2) * 16));
            uint32_t bh[4], bl[4];
            ldsm_x4t(bh, smb + VH_OFF + bx);
            ldsm_x4t(bl, smb + VL_OFF + bx);
            mma16816(C2[nt], a2h, bh);
            mma16816(C2[nt], a2h, bl);
            mma16816(C2[nt], a2l, bh);
            mma16816(C2[nt+1], a2h, bh + 2);
            mma16816(C2[nt+1], a2h, bl + 2);
            mma16816(C2[nt+1], a2l, bh + 2);
        }
    }
    rs0 += __shfl_xor_sync(0xffffffffu, rs0, 1);
    rs0 += __shfl_xor_sync(0xffffffffu, rs0, 2);
    rs1 += __shfl_xor_sync(0xffffffffu, rs1, 1);
    rs1 += __shfl_xor_sync(0xffffffffu, rs1, 2);
    if ((lid & 3) == 0) {   // unique owner per row -> plain add (no atomics)
        dnm[r0] += rs0;
        dnm[r1] += rs1;
    }
    __syncthreads();   // K planes dead; dnm rowsum complete

    // ---- stage S into dead K planes (hi/lo, swizzled); finalize dnm ----
    {
        const float* Sg = g_S[tile];
        #pragma unroll
        for (int i = 0; i < 8; i++) {
            const int idx = (tid + i * 256) * 2;
            const int e = idx >> 6;
            const int d = idx & 63;
            const float2 s2 = *(const float2*)(Sg + idx);
            uint32_t hi, lo;
            split_pack(s2.x, s2.y, hi, lo);
            const uint32_t x = sw((uint32_t)(e * 128 + d * 2));
            *(uint32_t*)(smc + KH_OFF + x) = hi;
            *(uint32_t*)(smc + KL_OFF + x) = lo;
        }
        if (tid < CHK) dnm[tid] = 1.f / (dnm[tid] + 1e-6f);
    }
    __syncthreads();

    // ---- MMA3: C2 += Qf @ S (S lives in K planes now) ----
    #pragma unroll
    for (int t = 0; t < 4; t++) {
        const int brow = t * 16 + g1 * 8 + gi;
        #pragma unroll
        for (int nt = 0; nt < 8; nt += 2) {
            const uint32_t bx = sw((uint32_t)(brow * 128 + (nt + q2) * 16));
            uint32_t bh[4], bl[4];
            ldsm_x4t(bh, smb + KH_OFF + bx);
            ldsm_x4t(bl, smb + KL_OFF + bx);
            mma16816(C2[nt], aqh[t], bh);
            mma16816(C2[nt], aqh[t], bl);
            mma16816(C2[nt], aql[t], bh);
            mma16816(C2[nt+1], aqh[t], bh + 2);
            mma16816(C2[nt+1], aqh[t], bl + 2);
            mma16816(C2[nt+1], aql[t], bh + 2);
        }
    }
    __syncthreads();

    // ---- epilogue: scale, stage over dead planes, coalesced STG ----
    {
        const float z0 = dnm[r0];
        const float z1 = dnm[r1];
        #pragma unroll
        for (int nt = 0; nt < 8; nt++) {
            const int cb = nt * 8 + (lid & 3) * 2;
            outb[r0 * 68 + cb]     = C2[nt][0] * z0;
            outb[r0 * 68 + cb + 1] = C2[nt][1] * z0;
            outb[r1 * 68 + cb]     = C2[nt][2] * z1;
            outb[r1 * 68 + cb + 1] = C2[nt][3] * z1;
        }
    }
    __syncthreads();

    const size_t obase = (((size_t)n * LSEQ + (size_t)c * CHK) * HEADS + h) * DDIM;
    {
        const int c4 = (tid & 15) << 2;
        #pragma unroll
        for (int i = 0; i < 8; i++) {
            const int p   = tid + i * 256;
            const int row = p >> 4;
            const float4 v4 = *(const float4*)(outb + row * 68 + c4);
            *(float4*)(out + obase + (size_t)row * ROWSTR + c4) = v4;
        }
    }
}

// ---------------------------------------------------------------------------
extern "C" void kernel_launch(void* const* d_in, const int* in_sizes, int n_in,
                              void* d_out, int out_size) {
    const float* Q = (const float*)d_in[0];
    const float* K = (const float*)d_in[1];
    const float* V = (const float*)d_in[2];
    float* out = (float*)d_out;

    cudaFuncSetAttribute(k_pass1, cudaFuncAttributeMaxDynamicSharedMemorySize, P1_SMEM);
    cudaFuncSetAttribute(k_pass3, cudaFuncAttributeMaxDynamicSharedMemorySize, P3_SMEM);

    k_pass1<<<NTILE, 256, P1_SMEM>>>(K, V);
    k_pass2<<<dim3(4, 64), 256>>>();
    k_pass3<<<NTILE, 256, P3_SMEM>>>(Q, K, V, out);
}